// round 5
// baseline (speedup 1.0000x reference)
#include <cuda_runtime.h>
#include <cuda_bf16.h>

#define BB 2
#define SS 2048
#define DM 1024
#define NH 16
#define DK 64

// Scratch (device-global arrays: allowed; no allocation APIs anywhere).
static __device__ float g_Q[BB * SS * DM];
static __device__ float g_K[BB * SS * DM];
static __device__ float g_V[BB * SS * DM];
static __device__ float g_C[BB * SS * DM];

// Split fp32 x into hi=bf16(x), lo=bf16(x-hi). Two (x,y) pairs packed into b32
// words (low half = even k element) for mma.sync bf16 operands.
__device__ __forceinline__ void split2(float x, float y, unsigned& whi, unsigned& wlo)
{
    __nv_bfloat16 hx = __float2bfloat16(x);
    __nv_bfloat16 hy = __float2bfloat16(y);
    __nv_bfloat16 lx = __float2bfloat16(x - __bfloat162float(hx));
    __nv_bfloat16 ly = __float2bfloat16(y - __bfloat162float(hy));
    whi = ((unsigned)__bfloat16_as_ushort(hy) << 16) | __bfloat16_as_ushort(hx);
    wlo = ((unsigned)__bfloat16_as_ushort(ly) << 16) | __bfloat16_as_ushort(lx);
}

#define MMA_BF16(acc, af, bf)                                                   \
    asm volatile(                                                               \
        "mma.sync.aligned.m16n8k16.row.col.f32.bf16.bf16.f32 "                  \
        "{%0,%1,%2,%3}, {%4,%5,%6,%7}, {%8,%9}, {%0,%1,%2,%3};"                 \
        : "+f"(acc[0]), "+f"(acc[1]), "+f"(acc[2]), "+f"(acc[3])                \
        : "r"(af[0]), "r"(af[1]), "r"(af[2]), "r"(af[3]), "r"(bf[0]), "r"(bf[1]))

// Batched 128x64-tile GEMM on bf16 2-split operands (3-term, ~fp32 accuracy).
// 256 threads = 8 warps (4 m x 2 n), warp tile 32x32 = 2x4 mma.m16n8k16 tiles.
// BK=32 (2 k16 steps), 1-deep register prefetch of gmem fp32.
//   BT=true : C = A * B^T ; BT=false : C = A * B
// Batch over grid.z = b*NH + h. Requires M%128==0, N%64==0, K%32==0.
// SMEM planes stored as b32 words (k-pairs), row stride 20 words:
// fragment LDS banks = 20*gid + tig + c -> bijective over the warp.
#define SW 20

template <bool BT>
__global__ __launch_bounds__(256) void gemm_bf16x2(
    const float* __restrict__ Ag, int lda, long sAb, long sAh,
    const float* __restrict__ Bg, int ldb, long sBb, long sBh,
    float* __restrict__ Cg, int ldc, long sCb, long sCh,
    int K, float scale, const float* __restrict__ bias)
{
    const int z = blockIdx.z;
    const int b = z / NH, h = z % NH;

    const float* A = Ag + (long)b * sAb + (long)h * sAh + (long)blockIdx.y * 128 * lda;
    const float* Bp = Bg + (long)b * sBb + (long)h * sBh;
    if (BT) Bp += (long)blockIdx.x * 64 * ldb;
    else    Bp += blockIdx.x * 64;
    float* C = Cg + (long)b * sCb + (long)h * sCh
                  + (long)blockIdx.y * 128 * ldc + blockIdx.x * 64;

    __shared__ unsigned AsH[128 * SW], AsL[128 * SW];
    __shared__ unsigned BsH[64 * SW],  BsL[64 * SW];

    const int tid  = threadIdx.x;
    const int lane = tid & 31;
    const int w    = tid >> 5;
    const int wm   = (w & 3) << 5;   // warp row offset (0,32,64,96)
    const int wn   = (w >> 2) << 5;  // warp col offset (0,32)
    const int gid  = lane >> 2, tig = lane & 3;

    // gmem load mapping
    const int am  = tid >> 3;         // 0..31 (A row within pass)
    const int ak  = (tid & 7) << 2;   // 0..28 (k quad)
    const int bnr = tid >> 3;         // BT: B row (n) within pass
    const int bkr = tid >> 4;         // NN: B row (k) within pass
    const int bn4 = (tid & 15) << 2;  // NN: n quad

    float acc[2][4][4];
    #pragma unroll
    for (int i = 0; i < 2; i++)
        #pragma unroll
        for (int j = 0; j < 4; j++)
            #pragma unroll
            for (int c = 0; c < 4; c++) acc[i][j][c] = 0.f;

    float4 ra[4], rb[2];

    // prefetch chunk 0
    #pragma unroll
    for (int r = 0; r < 4; r++)
        ra[r] = *(const float4*)(A + (long)(am + r * 32) * lda + ak);
    if (BT) {
        #pragma unroll
        for (int r = 0; r < 2; r++)
            rb[r] = *(const float4*)(Bp + (long)(bnr + r * 32) * ldb + ak);
    } else {
        #pragma unroll
        for (int r = 0; r < 2; r++)
            rb[r] = *(const float4*)(Bp + (long)(bkr + r * 16) * ldb + bn4);
    }

    for (int k0 = 0; k0 < K; k0 += 32) {
        // stage current chunk into smem (split to bf16 hi/lo planes)
        #pragma unroll
        for (int r = 0; r < 4; r++) {
            unsigned h0, l0, h1, l1;
            split2(ra[r].x, ra[r].y, h0, l0);
            split2(ra[r].z, ra[r].w, h1, l1);
            int base = (am + r * 32) * SW + (ak >> 1);
            AsH[base] = h0; AsH[base + 1] = h1;
            AsL[base] = l0; AsL[base + 1] = l1;
        }
        if (BT) {
            #pragma unroll
            for (int r = 0; r < 2; r++) {
                unsigned h0, l0, h1, l1;
                split2(rb[r].x, rb[r].y, h0, l0);
                split2(rb[r].z, rb[r].w, h1, l1);
                int base = (bnr + r * 32) * SW + (ak >> 1);
                BsH[base] = h0; BsH[base + 1] = h1;
                BsL[base] = l0; BsL[base + 1] = l1;
            }
        } else {
            // 4 consecutive n at fixed k -> scattered 16-bit stores
            unsigned short* bh = (unsigned short*)BsH;
            unsigned short* bl = (unsigned short*)BsL;
            #pragma unroll
            for (int r = 0; r < 2; r++) {
                int kk = bkr + r * 16;
                float vj[4] = {rb[r].x, rb[r].y, rb[r].z, rb[r].w};
                #pragma unroll
                for (int j = 0; j < 4; j++) {
                    __nv_bfloat16 hb = __float2bfloat16(vj[j]);
                    __nv_bfloat16 lb = __float2bfloat16(vj[j] - __bfloat162float(hb));
                    int idx = (bn4 + j) * (2 * SW) + kk;
                    bh[idx] = __bfloat16_as_ushort(hb);
                    bl[idx] = __bfloat16_as_ushort(lb);
                }
            }
        }
        __syncthreads();

        // prefetch next chunk
        if (k0 + 32 < K) {
            #pragma unroll
            for (int r = 0; r < 4; r++)
                ra[r] = *(const float4*)(A + (long)(am + r * 32) * lda + k0 + 32 + ak);
            if (BT) {
                #pragma unroll
                for (int r = 0; r < 2; r++)
                    rb[r] = *(const float4*)(Bp + (long)(bnr + r * 32) * ldb + k0 + 32 + ak);
            } else {
                #pragma unroll
                for (int r = 0; r < 2; r++)
                    rb[r] = *(const float4*)(Bp + (long)(k0 + 32 + bkr + r * 16) * ldb + bn4);
            }
        }

        // compute: 2 k16 steps
        #pragma unroll
        for (int s = 0; s < 2; s++) {
            unsigned afh[2][4], afl[2][4], bfh[4][2], bfl[4][2];
            #pragma unroll
            for (int mi = 0; mi < 2; mi++) {
                int r0 = wm + mi * 16 + gid;
                int c0 = 8 * s + tig;
                afh[mi][0] = AsH[r0 * SW + c0];
                afh[mi][1] = AsH[(r0 + 8) * SW + c0];
                afh[mi][2] = AsH[r0 * SW + c0 + 4];
                afh[mi][3] = AsH[(r0 + 8) * SW + c0 + 4];
                afl[mi][0] = AsL[r0 * SW + c0];
                afl[mi][1] = AsL[(r0 + 8) * SW + c0];
                afl[mi][2] = AsL[r0 * SW + c0 + 4];
                afl[mi][3] = AsL[(r0 + 8) * SW + c0 + 4];
            }
            #pragma unroll
            for (int ni = 0; ni < 4; ni++) {
                int cc = wn + ni * 8 + gid;
                int c0 = 8 * s + tig;
                bfh[ni][0] = BsH[cc * SW + c0];
                bfh[ni][1] = BsH[cc * SW + c0 + 4];
                bfl[ni][0] = BsL[cc * SW + c0];
                bfl[ni][1] = BsL[cc * SW + c0 + 4];
            }
            #pragma unroll
            for (int mi = 0; mi < 2; mi++)
                #pragma unroll
                for (int ni = 0; ni < 4; ni++) {
                    MMA_BF16(acc[mi][ni], afh[mi], bfh[ni]);
                    MMA_BF16(acc[mi][ni], afh[mi], bfl[ni]);
                    MMA_BF16(acc[mi][ni], afl[mi], bfh[ni]);
                }
        }
        __syncthreads();
    }

    // epilogue: c0:(g,2t) c1:(g,2t+1) c2:(g+8,2t) c3:(g+8,2t+1)
    #pragma unroll
    for (int mi = 0; mi < 2; mi++) {
        int r0 = wm + mi * 16 + gid;
        #pragma unroll
        for (int ni = 0; ni < 4; ni++) {
            int c0 = wn + ni * 8 + (tig << 1);
            float bv0 = 0.f, bv1 = 0.f;
            if (bias) {
                bv0 = bias[blockIdx.x * 64 + c0];
                bv1 = bias[blockIdx.x * 64 + c0 + 1];
            }
            float2 v0, v1;
            v0.x = fmaf(acc[mi][ni][0], scale, bv0);
            v0.y = fmaf(acc[mi][ni][1], scale, bv1);
            v1.x = fmaf(acc[mi][ni][2], scale, bv0);
            v1.y = fmaf(acc[mi][ni][3], scale, bv1);
            *(float2*)(C + (long)r0 * ldc + c0) = v0;
            *(float2*)(C + (long)(r0 + 8) * ldc + c0) = v1;
        }
    }
}

// Row softmax over rows of length SS=2048. One block (256 threads) per row,
// 8 elements per thread, in-place.
__global__ __launch_bounds__(256) void softmax_rows(float* __restrict__ attn)
{
    float* p = attn + (long)blockIdx.x * SS;
    const int tid = threadIdx.x;
    const int lane = tid & 31, wid = tid >> 5;
    __shared__ float red[8];

    float v[8];
    float m = -1e30f;
    #pragma unroll
    for (int i = 0; i < 8; i++) { v[i] = p[tid + i * 256]; m = fmaxf(m, v[i]); }
    #pragma unroll
    for (int o = 16; o > 0; o >>= 1) m = fmaxf(m, __shfl_xor_sync(0xffffffffu, m, o));
    if (lane == 0) red[wid] = m;
    __syncthreads();
    float mm = red[0];
    #pragma unroll
    for (int w = 1; w < 8; w++) mm = fmaxf(mm, red[w]);
    __syncthreads();

    float s = 0.f;
    #pragma unroll
    for (int i = 0; i < 8; i++) { v[i] = __expf(v[i] - mm); s += v[i]; }
    #pragma unroll
    for (int o = 16; o > 0; o >>= 1) s += __shfl_xor_sync(0xffffffffu, s, o);
    if (lane == 0) red[wid] = s;
    __syncthreads();
    float tot = red[0];
    #pragma unroll
    for (int w = 1; w < 8; w++) tot += red[w];

    float inv = 1.f / tot;
    #pragma unroll
    for (int i = 0; i < 8; i++) p[tid + i * 256] = v[i] * inv;
}

extern "C" void kernel_launch(void* const* d_in, const int* in_sizes, int n_in,
                              void* d_out, int out_size)
{
    (void)in_sizes; (void)n_in; (void)out_size;

    const float* q  = (const float*)d_in[0];
    const float* k  = (const float*)d_in[1];
    const float* vv = (const float*)d_in[2];
    const float* Wq = (const float*)d_in[3];
    const float* bq = (const float*)d_in[4];
    const float* Wk = (const float*)d_in[5];
    const float* bk = (const float*)d_in[6];
    const float* Wv = (const float*)d_in[7];
    const float* bv = (const float*)d_in[8];
    const float* Wo = (const float*)d_in[9];
    const float* bo = (const float*)d_in[10];

    float* out  = (float*)d_out;                 // [B,S,D] = 4,194,304 floats
    float* attn = out + (long)BB * SS * DM;      // [B,H,S,S] = 134,217,728 floats

    float *gQ, *gK, *gV, *gC;
    cudaGetSymbolAddress((void**)&gQ, g_Q);
    cudaGetSymbolAddress((void**)&gK, g_K);
    cudaGetSymbolAddress((void**)&gV, g_V);
    cudaGetSymbolAddress((void**)&gC, g_C);

    dim3 blk(256);
    dim3 gproj(DM / 64, (BB * SS) / 128, 1);     // (16, 32)

    // Q/K/V projections: X @ W^T + b  (NT, M=4096, N=1024, K=1024)
    gemm_bf16x2<true><<<gproj, blk>>>(q,  DM, 0, 0, Wq, DM, 0, 0, gQ, DM, 0, 0, DM, 1.f, bq);
    gemm_bf16x2<true><<<gproj, blk>>>(k,  DM, 0, 0, Wk, DM, 0, 0, gK, DM, 0, 0, DM, 1.f, bk);
    gemm_bf16x2<true><<<gproj, blk>>>(vv, DM, 0, 0, Wv, DM, 0, 0, gV, DM, 0, 0, DM, 1.f, bv);

    // Scores: attn[b,h,i,j] = (Qh_i . Kh_j) / 8   (NT, M=N=2048, K=64, batch=32)
    dim3 gsc(SS / 64, SS / 128, BB * NH);
    gemm_bf16x2<true><<<gsc, blk>>>(gQ, DM, (long)SS * DM, DK,
                                    gK, DM, (long)SS * DM, DK,
                                    attn, SS, (long)NH * SS * SS, (long)SS * SS,
                                    DK, 0.125f, nullptr);

    // Softmax in place, row-wise over last dim.
    softmax_rows<<<BB * NH * SS, blk>>>(attn);

    // Context: ctx[b,i,h*64+d] = sum_j P[b,h,i,j] * V[b,j,h*64+d]
    // (NN, M=2048, N=64, K=2048, batch=32)
    dim3 gct(1, SS / 128, BB * NH);
    gemm_bf16x2<false><<<gct, blk>>>(attn, SS, (long)NH * SS * SS, (long)SS * SS,
                                     gV, DM, (long)SS * DM, DK,
                                     gC, DM, (long)SS * DM, DK,
                                     SS, 1.f, nullptr);

    // Output projection: out = ctx @ Wo^T + bo
    gemm_bf16x2<true><<<gproj, blk>>>(gC, DM, 0, 0, Wo, DM, 0, 0, out, DM, 0, 0, DM, 1.f, bo);
}

// round 9
// speedup vs baseline: 1.2125x; 1.2125x over previous
#include <cuda_runtime.h>
#include <cuda_bf16.h>
#include <cstdint>

#define BB 2
#define SS 2048
#define DM 1024
#define NH 16
#define DK 64

typedef unsigned short u16;
typedef unsigned int   u32;

// ---- bf16 hi/lo plane scratch (device globals; no allocation APIs) ----
static __device__ u16 g_Qh [BB*SS*DM], g_Ql [BB*SS*DM];
static __device__ u16 g_Kh [BB*SS*DM], g_Kl [BB*SS*DM];
static __device__ u16 g_Vth[BB*SS*DM], g_Vtl[BB*SS*DM];   // [b][h][dk][s]
static __device__ u16 g_Ch [BB*SS*DM], g_Cl [BB*SS*DM];
static __device__ u16 g_Wh [4*DM*DM],  g_Wl [4*DM*DM];

// ---------------- helpers ----------------
__device__ __forceinline__ u32 smem_u32(const void* p) {
    u32 a;
    asm("{ .reg .u64 t; cvta.to.shared.u64 t, %1; cvt.u32.u64 %0, t; }"
        : "=r"(a) : "l"(p));
    return a;
}
// SW128 swizzle on byte offsets (XORs bits 4-6 with row&7 for 128B rows)
#define SWZ(o) ((o) ^ (((o) >> 3) & 0x70))

__device__ __forceinline__ void split1(float v, u16& h, u16& l) {
    __nv_bfloat16 hb = __float2bfloat16(v);
    h = __bfloat16_as_ushort(hb);
    l = __bfloat16_as_ushort(__float2bfloat16(v - __bfloat162float(hb)));
}

__device__ __forceinline__ void cpa16(u32 s, const void* g) {
    asm volatile("cp.async.cg.shared.global [%0], [%1], 16;" :: "r"(s), "l"(g));
}
__device__ __forceinline__ void cpa_commit() {
    asm volatile("cp.async.commit_group;" ::: "memory");
}
__device__ __forceinline__ void cpa_wait1() {
    asm volatile("cp.async.wait_group 1;" ::: "memory");
}
__device__ __forceinline__ void cpa_wait0() {
    asm volatile("cp.async.wait_group 0;" ::: "memory");
}
__device__ __forceinline__ void ldsm4(u32 a, u32& r0, u32& r1, u32& r2, u32& r3) {
    asm volatile("ldmatrix.sync.aligned.m8n8.x4.shared.b16 {%0,%1,%2,%3}, [%4];"
        : "=r"(r0), "=r"(r1), "=r"(r2), "=r"(r3) : "r"(a));
}

#define MMA_BF16(acc, af, bf)                                                   \
    asm volatile(                                                               \
        "mma.sync.aligned.m16n8k16.row.col.f32.bf16.bf16.f32 "                  \
        "{%0,%1,%2,%3}, {%4,%5,%6,%7}, {%8,%9}, {%0,%1,%2,%3};"                 \
        : "+f"(acc[0]), "+f"(acc[1]), "+f"(acc[2]), "+f"(acc[3])                \
        : "r"(af[0]), "r"(af[1]), "r"(af[2]), "r"(af[3]), "r"(bf[0]), "r"(bf[1]))

// ---------------- GEMM: C[128x64 tile] = A * B^T (NT), bf16x2 3-term ----------------
// AFP32=1: A is fp32 gmem, split in-kernel. AFP32=0: A is pre-split planes (cp.async).
// B always pre-split planes (cp.async). BK=64 double-buffered SW128 smem; ldmatrix frags.
// OUTM: 0 = fp32 C (+scale,+bias) ; 1 = bf16 hi/lo planes (+scale,+bias) ;
//       2 = transposed per-head planes (V^T) via smem staging.
// Requires M%128==0, N%64==0, K%64==0.
template <int AFP32, int OUTM>
__global__ __launch_bounds__(256) void gemm_p(
    const float* __restrict__ Af, const u16* __restrict__ Aph, const u16* __restrict__ Apl,
    long lda, long sAb, long sAh,
    const u16* __restrict__ Bph, const u16* __restrict__ Bpl,
    long ldb, long sBb, long sBh,
    float* __restrict__ Cf, u16* __restrict__ Cph, u16* __restrict__ Cpl,
    long ldc, long sCb, long sCh,
    int K, float scale, const float* __restrict__ bias)
{
    extern __shared__ char dsm[];
    const u32 sbase = smem_u32(dsm);

    const int tid = threadIdx.x, lane = tid & 31, w = tid >> 5;
    const int wm = (w & 3) << 5, wn = (w >> 2) << 5;
    const int g = lane >> 2, t = lane & 3;
    const int z = blockIdx.z, b = z / NH, h = z % NH;

    const long aoff = (long)b * sAb + (long)h * sAh + (long)blockIdx.y * 128 * lda;
    const float* Afp = Af ? (Af + aoff) : nullptr;
    const u16* AhG = Aph ? (Aph + aoff) : nullptr;
    const u16* AlG = Apl ? (Apl + aoff) : nullptr;
    const long boff = (long)b * sBb + (long)h * sBh + (long)blockIdx.x * 64 * ldb;
    const u16* BhG = Bph + boff;
    const u16* BlG = Bpl + boff;

    // buffer layout (bytes): buf*49152 + {Ah:0, Al:16384, Bh:32768, Bl:40960}
    float acc[2][4][4];
    #pragma unroll
    for (int i = 0; i < 2; i++)
        #pragma unroll
        for (int j = 0; j < 4; j++)
            #pragma unroll
            for (int c = 0; c < 4; c++) acc[i][j][c] = 0.f;

    // unswizzled per-thread fragment byte offsets (add s*32, then SWZ)
    u32 a_base[2], b_base[2];
    #pragma unroll
    for (int mi = 0; mi < 2; mi++) {
        int row = wm + mi * 16 + (lane & 15);
        a_base[mi] = (u32)(row * 128 + (lane >> 4) * 16);
    }
    #pragma unroll
    for (int np = 0; np < 2; np++) {
        int n = wn + np * 16 + (lane & 7) + ((lane >> 4) << 3);
        b_base[np] = (u32)(n * 128 + ((lane >> 3) & 1) * 16);
    }

    auto issueB = [&](int c, int buf) {
        u32 bh = sbase + buf * 49152 + 32768, bl = bh + 8192;
        const u16* gh = BhG + c * 64;
        const u16* gl = BlG + c * 64;
        #pragma unroll
        for (int it = 0; it < 2; it++) {
            int i = it * 256 + tid;
            int row = i >> 3, cc = i & 7;
            u32 so = SWZ((u32)(row * 128 + cc * 16));
            cpa16(bh + so, gh + (long)row * ldb + cc * 8);
            cpa16(bl + so, gl + (long)row * ldb + cc * 8);
        }
    };
    auto issueA = [&](int c, int buf) {   // planes path
        u32 ah = sbase + buf * 49152, al = ah + 16384;
        const u16* gh = AhG + c * 64;
        const u16* gl = AlG + c * 64;
        #pragma unroll
        for (int it = 0; it < 4; it++) {
            int i = it * 256 + tid;
            int row = i >> 3, cc = i & 7;
            u32 so = SWZ((u32)(row * 128 + cc * 16));
            cpa16(ah + so, gh + (long)row * lda + cc * 8);
            cpa16(al + so, gl + (long)row * lda + cc * 8);
        }
    };

    float4 ra[8];
    auto ldgA = [&](int c) {              // fp32 path prefetch
        #pragma unroll
        for (int it = 0; it < 8; it++) {
            int i = it * 256 + tid;
            int row = i >> 4, cq = (i & 15) << 2;
            ra[it] = *(const float4*)(Afp + (long)row * lda + c * 64 + cq);
        }
    };
    auto stsA = [&](int buf) {            // fp32 path: split + store both planes
        char* ahp = dsm + buf * 49152;
        char* alp = ahp + 16384;
        #pragma unroll
        for (int it = 0; it < 8; it++) {
            int i = it * 256 + tid;
            int row = i >> 4, cq = (i & 15) << 2;
            u16 h0, l0, h1, l1, h2, l2, h3, l3;
            split1(ra[it].x, h0, l0); split1(ra[it].y, h1, l1);
            split1(ra[it].z, h2, l2); split1(ra[it].w, h3, l3);
            u32 so = SWZ((u32)(row * 128 + cq * 2));
            *(uint2*)(ahp + so) = make_uint2(h0 | ((u32)h1 << 16), h2 | ((u32)h3 << 16));
            *(uint2*)(alp + so) = make_uint2(l0 | ((u32)l1 << 16), l2 | ((u32)l3 << 16));
        }
    };

    auto compute = [&](int buf) {
        u32 ah = sbase + buf * 49152, al = ah + 16384;
        u32 bh = ah + 32768, bl = ah + 40960;
        #pragma unroll
        for (int s = 0; s < 4; s++) {
            u32 afh[2][4], afl[2][4], bfh[4][2], bfl[4][2];
            #pragma unroll
            for (int mi = 0; mi < 2; mi++) {
                u32 o = SWZ(a_base[mi] + s * 32);
                ldsm4(ah + o, afh[mi][0], afh[mi][1], afh[mi][2], afh[mi][3]);
                ldsm4(al + o, afl[mi][0], afl[mi][1], afl[mi][2], afl[mi][3]);
            }
            #pragma unroll
            for (int np = 0; np < 2; np++) {
                u32 o = SWZ(b_base[np] + s * 32);
                u32 r0, r1, r2, r3;
                ldsm4(bh + o, r0, r1, r2, r3);
                bfh[np * 2][0] = r0; bfh[np * 2][1] = r1;
                bfh[np * 2 + 1][0] = r2; bfh[np * 2 + 1][1] = r3;
                ldsm4(bl + o, r0, r1, r2, r3);
                bfl[np * 2][0] = r0; bfl[np * 2][1] = r1;
                bfl[np * 2 + 1][0] = r2; bfl[np * 2 + 1][1] = r3;
            }
            #pragma unroll
            for (int mi = 0; mi < 2; mi++)
                #pragma unroll
                for (int ni = 0; ni < 4; ni++) {
                    MMA_BF16(acc[mi][ni], afh[mi], bfh[ni]);
                    MMA_BF16(acc[mi][ni], afh[mi], bfl[ni]);
                    MMA_BF16(acc[mi][ni], afl[mi], bfh[ni]);
                }
        }
    };

    const int nch = K >> 6;
    if (AFP32) ldgA(0); else issueA(0, 0);
    issueB(0, 0);
    cpa_commit();

    for (int c = 0; c < nch; c++) {
        const int buf = c & 1;
        if (AFP32) stsA(buf);
        if (c + 1 < nch) {
            const int nb = (c + 1) & 1;
            if (!AFP32) issueA(c + 1, nb);
            issueB(c + 1, nb);
            cpa_commit();
            if (AFP32) ldgA(c + 1);
            cpa_wait1();
        } else {
            cpa_wait0();
        }
        __syncthreads();
        compute(buf);
        __syncthreads();
    }

    // ---------------- epilogues ----------------
    if (OUTM == 0) {
        float* C = Cf + (long)b * sCb + (long)h * sCh
                      + (long)blockIdx.y * 128 * ldc + blockIdx.x * 64;
        #pragma unroll
        for (int mi = 0; mi < 2; mi++) {
            int r0 = wm + mi * 16 + g;
            #pragma unroll
            for (int ni = 0; ni < 4; ni++) {
                int c0 = wn + ni * 8 + (t << 1);
                float bv0 = 0.f, bv1 = 0.f;
                if (bias) {
                    bv0 = bias[blockIdx.x * 64 + c0];
                    bv1 = bias[blockIdx.x * 64 + c0 + 1];
                }
                float2 v0, v1;
                v0.x = fmaf(acc[mi][ni][0], scale, bv0);
                v0.y = fmaf(acc[mi][ni][1], scale, bv1);
                v1.x = fmaf(acc[mi][ni][2], scale, bv0);
                v1.y = fmaf(acc[mi][ni][3], scale, bv1);
                *(float2*)(C + (long)r0 * ldc + c0) = v0;
                *(float2*)(C + (long)(r0 + 8) * ldc + c0) = v1;
            }
        }
    } else if (OUTM == 1) {
        u16* Ph = Cph + (long)b * sCb + (long)h * sCh
                      + (long)blockIdx.y * 128 * ldc + blockIdx.x * 64;
        u16* Pl = Cpl + (long)b * sCb + (long)h * sCh
                      + (long)blockIdx.y * 128 * ldc + blockIdx.x * 64;
        #pragma unroll
        for (int mi = 0; mi < 2; mi++) {
            int r0 = wm + mi * 16 + g;
            #pragma unroll
            for (int ni = 0; ni < 4; ni++) {
                int c0 = wn + ni * 8 + (t << 1);
                float bv0 = 0.f, bv1 = 0.f;
                if (bias) {
                    bv0 = bias[blockIdx.x * 64 + c0];
                    bv1 = bias[blockIdx.x * 64 + c0 + 1];
                }
                float v00 = fmaf(acc[mi][ni][0], scale, bv0);
                float v01 = fmaf(acc[mi][ni][1], scale, bv1);
                float v10 = fmaf(acc[mi][ni][2], scale, bv0);
                float v11 = fmaf(acc[mi][ni][3], scale, bv1);
                u16 h00, l00, h01, l01, h10, l10, h11, l11;
                split1(v00, h00, l00); split1(v01, h01, l01);
                split1(v10, h10, l10); split1(v11, h11, l11);
                *(u32*)(Ph + (long)r0 * ldc + c0)       = h00 | ((u32)h01 << 16);
                *(u32*)(Pl + (long)r0 * ldc + c0)       = l00 | ((u32)l01 << 16);
                *(u32*)(Ph + (long)(r0 + 8) * ldc + c0) = h10 | ((u32)h11 << 16);
                *(u32*)(Pl + (long)(r0 + 8) * ldc + c0) = l10 | ((u32)l11 << 16);
            }
        }
    } else {
        // OUTM==2: V^T per head; stage acc through smem fp32 then split-store.
        float* epi = (float*)dsm;
        #pragma unroll
        for (int mi = 0; mi < 2; mi++) {
            int r0 = wm + mi * 16 + g;
            #pragma unroll
            for (int ni = 0; ni < 4; ni++) {
                int c0 = wn + ni * 8 + (t << 1);
                epi[r0 * 65 + c0]           = acc[mi][ni][0];
                epi[r0 * 65 + c0 + 1]       = acc[mi][ni][1];
                epi[(r0 + 8) * 65 + c0]     = acc[mi][ni][2];
                epi[(r0 + 8) * 65 + c0 + 1] = acc[mi][ni][3];
            }
        }
        __syncthreads();
        long base = ((long)(blockIdx.y >> 4) * NH + blockIdx.x) * DK * SS
                  + (long)(blockIdx.y & 15) * 128;
        #pragma unroll
        for (int it = 0; it < 32; it++) {
            int i = it * 256 + tid;
            int n = i >> 7, m = i & 127;
            float v = epi[m * 65 + n] * scale;
            if (bias) v += bias[blockIdx.x * 64 + n];
            u16 hh, ll;
            split1(v, hh, ll);
            Cph[base + (long)n * SS + m] = hh;
            Cpl[base + (long)n * SS + m] = ll;
        }
    }
}

// ---------------- weight converter: fp32 -> bf16 hi/lo planes ----------------
__global__ __launch_bounds__(256) void splitw(const float* __restrict__ x,
                                              u16* __restrict__ ph, u16* __restrict__ pl)
{
    int i = (blockIdx.x * 256 + threadIdx.x) * 4;
    float4 v = *(const float4*)(x + i);
    u16 h0, l0, h1, l1, h2, l2, h3, l3;
    split1(v.x, h0, l0); split1(v.y, h1, l1);
    split1(v.z, h2, l2); split1(v.w, h3, l3);
    *(uint2*)(ph + i) = make_uint2(h0 | ((u32)h1 << 16), h2 | ((u32)h3 << 16));
    *(uint2*)(pl + i) = make_uint2(l0 | ((u32)l1 << 16), l2 | ((u32)l3 << 16));
}

// ---------------- softmax (unchanged; proven) ----------------
__global__ __launch_bounds__(256) void softmax_rows(float* __restrict__ attn)
{
    float* p = attn + (long)blockIdx.x * SS;
    const int tid = threadIdx.x;
    const int lane = tid & 31, wrp = tid >> 5;
    __shared__ float red[8];

    float v[8];
    float m = -1e30f;
    #pragma unroll
    for (int i = 0; i < 8; i++) { v[i] = p[tid + i * 256]; m = fmaxf(m, v[i]); }
    #pragma unroll
    for (int o = 16; o > 0; o >>= 1) m = fmaxf(m, __shfl_xor_sync(0xffffffffu, m, o));
    if (lane == 0) red[wrp] = m;
    __syncthreads();
    float mm = red[0];
    #pragma unroll
    for (int w = 1; w < 8; w++) mm = fmaxf(mm, red[w]);
    __syncthreads();

    float s = 0.f;
    #pragma unroll
    for (int i = 0; i < 8; i++) { v[i] = __expf(v[i] - mm); s += v[i]; }
    #pragma unroll
    for (int o = 16; o > 0; o >>= 1) s += __shfl_xor_sync(0xffffffffu, s, o);
    if (lane == 0) red[wrp] = s;
    __syncthreads();
    float tot = red[0];
    #pragma unroll
    for (int w = 1; w < 8; w++) tot += red[w];

    float inv = 1.f / tot;
    #pragma unroll
    for (int i = 0; i < 8; i++) p[tid + i * 256] = v[i] * inv;
}

extern "C" void kernel_launch(void* const* d_in, const int* in_sizes, int n_in,
                              void* d_out, int out_size)
{
    (void)in_sizes; (void)n_in; (void)out_size;

    const float* q  = (const float*)d_in[0];
    const float* k  = (const float*)d_in[1];
    const float* vv = (const float*)d_in[2];
    const float* Wq = (const float*)d_in[3];
    const float* bq = (const float*)d_in[4];
    const float* Wk = (const float*)d_in[5];
    const float* bk = (const float*)d_in[6];
    const float* Wv = (const float*)d_in[7];
    const float* bv = (const float*)d_in[8];
    const float* Wo = (const float*)d_in[9];
    const float* bo = (const float*)d_in[10];

    float* out  = (float*)d_out;                 // [B,S,D]
    float* attn = out + (long)BB * SS * DM;      // [B,H,S,S]

    u16 *Qh, *Ql, *Kh, *Kl, *Vth, *Vtl, *Ch, *Cl, *Wh, *Wl;
    cudaGetSymbolAddress((void**)&Qh,  g_Qh);  cudaGetSymbolAddress((void**)&Ql,  g_Ql);
    cudaGetSymbolAddress((void**)&Kh,  g_Kh);  cudaGetSymbolAddress((void**)&Kl,  g_Kl);
    cudaGetSymbolAddress((void**)&Vth, g_Vth); cudaGetSymbolAddress((void**)&Vtl, g_Vtl);
    cudaGetSymbolAddress((void**)&Ch,  g_Ch);  cudaGetSymbolAddress((void**)&Cl,  g_Cl);
    cudaGetSymbolAddress((void**)&Wh,  g_Wh);  cudaGetSymbolAddress((void**)&Wl,  g_Wl);

    const int shm = 98304;  // 96 KB double-buffered operand smem
    cudaFuncSetAttribute(gemm_p<0,0>, cudaFuncAttributeMaxDynamicSharedMemorySize, shm);
    cudaFuncSetAttribute(gemm_p<1,1>, cudaFuncAttributeMaxDynamicSharedMemorySize, shm);
    cudaFuncSetAttribute(gemm_p<1,2>, cudaFuncAttributeMaxDynamicSharedMemorySize, shm);

    dim3 blk(256);

    // weight planes
    splitw<<<DM * DM / 1024, blk>>>(Wq, Wh + 0 * DM * DM, Wl + 0 * DM * DM);
    splitw<<<DM * DM / 1024, blk>>>(Wk, Wh + 1 * DM * DM, Wl + 1 * DM * DM);
    splitw<<<DM * DM / 1024, blk>>>(Wv, Wh + 2 * DM * DM, Wl + 2 * DM * DM);
    splitw<<<DM * DM / 1024, blk>>>(Wo, Wh + 3 * DM * DM, Wl + 3 * DM * DM);

    dim3 gproj(DM / 64, (BB * SS) / 128, 1);     // (16, 32)

    // Q/K projections -> planes
    gemm_p<1,1><<<gproj, blk, shm>>>(q, nullptr, nullptr, DM, 0, 0,
                                     Wh + 0 * DM * DM, Wl + 0 * DM * DM, DM, 0, 0,
                                     nullptr, Qh, Ql, DM, 0, 0, DM, 1.f, bq);
    gemm_p<1,1><<<gproj, blk, shm>>>(k, nullptr, nullptr, DM, 0, 0,
                                     Wh + 1 * DM * DM, Wl + 1 * DM * DM, DM, 0, 0,
                                     nullptr, Kh, Kl, DM, 0, 0, DM, 1.f, bk);
    // V projection -> V^T planes (per head)
    gemm_p<1,2><<<gproj, blk, shm>>>(vv, nullptr, nullptr, DM, 0, 0,
                                     Wh + 2 * DM * DM, Wl + 2 * DM * DM, DM, 0, 0,
                                     nullptr, Vth, Vtl, 0, 0, 0, DM, 1.f, bv);

    // scores: attn = (Q K^T)/8  (planes x planes, K=DK)
    dim3 gsc(SS / 64, SS / 128, BB * NH);
    gemm_p<0,0><<<gsc, blk, shm>>>(nullptr, Qh, Ql, DM, (long)SS * DM, DK,
                                   Kh, Kl, DM, (long)SS * DM, DK,
                                   attn, nullptr, nullptr, SS,
                                   (long)NH * SS * SS, (long)SS * SS,
                                   DK, 0.125f, nullptr);

    softmax_rows<<<BB * NH * SS, blk>>>(attn);

    // PV: ctx planes = attn(fp32) @ Vt^T  (K=SS)
    dim3 gct(1, SS / 128, BB * NH);
    gemm_p<1,1><<<gct, blk, shm>>>(attn, nullptr, nullptr, SS,
                                   (long)NH * SS * SS, (long)SS * SS,
                                   Vth, Vtl, SS, (long)SS * DM, (long)DK * SS,
                                   nullptr, Ch, Cl, DM, (long)SS * DM, DK,
                                   SS, 1.f, nullptr);

    // output projection: out = ctx @ Wo^T + bo  (planes x planes)
    gemm_p<0,0><<<gproj, blk, shm>>>(nullptr, Ch, Cl, DM, 0, 0,
                                     Wh + 3 * DM * DM, Wl + 3 * DM * DM, DM, 0, 0,
                                     out, nullptr, nullptr, DM, 0, 0,
                                     DM, 1.f, bo);
}

// round 13
// speedup vs baseline: 1.2616x; 1.0405x over previous
#include <cuda_runtime.h>
#include <cuda_bf16.h>
#include <cstdint>

#define BB 2
#define SS 2048
#define DM 1024
#define NH 16
#define DK 64

typedef unsigned short u16;
typedef unsigned int   u32;

// ---- bf16 hi/lo plane scratch (device globals; no allocation APIs) ----
static __device__ u16 g_Qh [BB*SS*DM], g_Ql [BB*SS*DM];
static __device__ u16 g_Kh [BB*SS*DM], g_Kl [BB*SS*DM];
static __device__ u16 g_Vth[BB*SS*DM], g_Vtl[BB*SS*DM];   // [b][h][dk][s]
static __device__ u16 g_Ch [BB*SS*DM], g_Cl [BB*SS*DM];
static __device__ u16 g_Wh [4*DM*DM],  g_Wl [4*DM*DM];

// ---------------- helpers ----------------
__device__ __forceinline__ u32 smem_u32(const void* p) {
    u32 a;
    asm("{ .reg .u64 t; cvta.to.shared.u64 t, %1; cvt.u32.u64 %0, t; }"
        : "=r"(a) : "l"(p));
    return a;
}
#define SWZ(o) ((o) ^ (((o) >> 3) & 0x70))

__device__ __forceinline__ void split1(float v, u16& h, u16& l) {
    __nv_bfloat16 hb = __float2bfloat16(v);
    h = __bfloat16_as_ushort(hb);
    l = __bfloat16_as_ushort(__float2bfloat16(v - __bfloat162float(hb)));
}

__device__ __forceinline__ void cpa16(u32 s, const void* g) {
    asm volatile("cp.async.cg.shared.global [%0], [%1], 16;" :: "r"(s), "l"(g));
}
__device__ __forceinline__ void cpa_commit() {
    asm volatile("cp.async.commit_group;" ::: "memory");
}
__device__ __forceinline__ void cpa_wait1() {
    asm volatile("cp.async.wait_group 1;" ::: "memory");
}
__device__ __forceinline__ void cpa_wait0() {
    asm volatile("cp.async.wait_group 0;" ::: "memory");
}
__device__ __forceinline__ void ldsm4(u32 a, u32& r0, u32& r1, u32& r2, u32& r3) {
    asm volatile("ldmatrix.sync.aligned.m8n8.x4.shared.b16 {%0,%1,%2,%3}, [%4];"
        : "=r"(r0), "=r"(r1), "=r"(r2), "=r"(r3) : "r"(a));
}

#define MMA_BF16(acc, af, bf)                                                   \
    asm volatile(                                                               \
        "mma.sync.aligned.m16n8k16.row.col.f32.bf16.bf16.f32 "                  \
        "{%0,%1,%2,%3}, {%4,%5,%6,%7}, {%8,%9}, {%0,%1,%2,%3};"                 \
        : "+f"(acc[0]), "+f"(acc[1]), "+f"(acc[2]), "+f"(acc[3])                \
        : "r"(af[0]), "r"(af[1]), "r"(af[2]), "r"(af[3]), "r"(bf[0]), "r"(bf[1]))

// ---------------- GEMM: C[128x64 tile] = A * B^T (NT), bf16x2 3-term ----------------
// (unchanged, proven in round 9; used for projections + output projection)
template <int AFP32, int OUTM>
__global__ __launch_bounds__(256) void gemm_p(
    const float* __restrict__ Af, const u16* __restrict__ Aph, const u16* __restrict__ Apl,
    long lda, long sAb, long sAh,
    const u16* __restrict__ Bph, const u16* __restrict__ Bpl,
    long ldb, long sBb, long sBh,
    float* __restrict__ Cf, u16* __restrict__ Cph, u16* __restrict__ Cpl,
    long ldc, long sCb, long sCh,
    int K, float scale, const float* __restrict__ bias)
{
    extern __shared__ char dsm[];
    const u32 sbase = smem_u32(dsm);

    const int tid = threadIdx.x, lane = tid & 31, w = tid >> 5;
    const int wm = (w & 3) << 5, wn = (w >> 2) << 5;
    const int g = lane >> 2, t = lane & 3;
    const int z = blockIdx.z, b = z / NH, h = z % NH;

    const long aoff = (long)b * sAb + (long)h * sAh + (long)blockIdx.y * 128 * lda;
    const float* Afp = Af ? (Af + aoff) : nullptr;
    const u16* AhG = Aph ? (Aph + aoff) : nullptr;
    const u16* AlG = Apl ? (Apl + aoff) : nullptr;
    const long boff = (long)b * sBb + (long)h * sBh + (long)blockIdx.x * 64 * ldb;
    const u16* BhG = Bph + boff;
    const u16* BlG = Bpl + boff;

    float acc[2][4][4];
    #pragma unroll
    for (int i = 0; i < 2; i++)
        #pragma unroll
        for (int j = 0; j < 4; j++)
            #pragma unroll
            for (int c = 0; c < 4; c++) acc[i][j][c] = 0.f;

    u32 a_base[2], b_base[2];
    #pragma unroll
    for (int mi = 0; mi < 2; mi++) {
        int row = wm + mi * 16 + (lane & 15);
        a_base[mi] = (u32)(row * 128 + (lane >> 4) * 16);
    }
    #pragma unroll
    for (int np = 0; np < 2; np++) {
        int n = wn + np * 16 + (lane & 7) + ((lane >> 4) << 3);
        b_base[np] = (u32)(n * 128 + ((lane >> 3) & 1) * 16);
    }

    auto issueB = [&](int c, int buf) {
        u32 bh = sbase + buf * 49152 + 32768, bl = bh + 8192;
        const u16* gh = BhG + c * 64;
        const u16* gl = BlG + c * 64;
        #pragma unroll
        for (int it = 0; it < 2; it++) {
            int i = it * 256 + tid;
            int row = i >> 3, cc = i & 7;
            u32 so = SWZ((u32)(row * 128 + cc * 16));
            cpa16(bh + so, gh + (long)row * ldb + cc * 8);
            cpa16(bl + so, gl + (long)row * ldb + cc * 8);
        }
    };
    auto issueA = [&](int c, int buf) {
        u32 ah = sbase + buf * 49152, al = ah + 16384;
        const u16* gh = AhG + c * 64;
        const u16* gl = AlG + c * 64;
        #pragma unroll
        for (int it = 0; it < 4; it++) {
            int i = it * 256 + tid;
            int row = i >> 3, cc = i & 7;
            u32 so = SWZ((u32)(row * 128 + cc * 16));
            cpa16(ah + so, gh + (long)row * lda + cc * 8);
            cpa16(al + so, gl + (long)row * lda + cc * 8);
        }
    };

    float4 ra[8];
    auto ldgA = [&](int c) {
        #pragma unroll
        for (int it = 0; it < 8; it++) {
            int i = it * 256 + tid;
            int row = i >> 4, cq = (i & 15) << 2;
            ra[it] = *(const float4*)(Afp + (long)row * lda + c * 64 + cq);
        }
    };
    auto stsA = [&](int buf) {
        char* ahp = dsm + buf * 49152;
        char* alp = ahp + 16384;
        #pragma unroll
        for (int it = 0; it < 8; it++) {
            int i = it * 256 + tid;
            int row = i >> 4, cq = (i & 15) << 2;
            u16 h0, l0, h1, l1, h2, l2, h3, l3;
            split1(ra[it].x, h0, l0); split1(ra[it].y, h1, l1);
            split1(ra[it].z, h2, l2); split1(ra[it].w, h3, l3);
            u32 so = SWZ((u32)(row * 128 + cq * 2));
            *(uint2*)(ahp + so) = make_uint2(h0 | ((u32)h1 << 16), h2 | ((u32)h3 << 16));
            *(uint2*)(alp + so) = make_uint2(l0 | ((u32)l1 << 16), l2 | ((u32)l3 << 16));
        }
    };

    auto compute = [&](int buf) {
        u32 ah = sbase + buf * 49152, al = ah + 16384;
        u32 bh = ah + 32768, bl = ah + 40960;
        #pragma unroll
        for (int s = 0; s < 4; s++) {
            u32 afh[2][4], afl[2][4], bfh[4][2], bfl[4][2];
            #pragma unroll
            for (int mi = 0; mi < 2; mi++) {
                u32 o = SWZ(a_base[mi] + s * 32);
                ldsm4(ah + o, afh[mi][0], afh[mi][1], afh[mi][2], afh[mi][3]);
                ldsm4(al + o, afl[mi][0], afl[mi][1], afl[mi][2], afl[mi][3]);
            }
            #pragma unroll
            for (int np = 0; np < 2; np++) {
                u32 o = SWZ(b_base[np] + s * 32);
                u32 r0, r1, r2, r3;
                ldsm4(bh + o, r0, r1, r2, r3);
                bfh[np * 2][0] = r0; bfh[np * 2][1] = r1;
                bfh[np * 2 + 1][0] = r2; bfh[np * 2 + 1][1] = r3;
                ldsm4(bl + o, r0, r1, r2, r3);
                bfl[np * 2][0] = r0; bfl[np * 2][1] = r1;
                bfl[np * 2 + 1][0] = r2; bfl[np * 2 + 1][1] = r3;
            }
            #pragma unroll
            for (int mi = 0; mi < 2; mi++)
                #pragma unroll
                for (int ni = 0; ni < 4; ni++) {
                    MMA_BF16(acc[mi][ni], afh[mi], bfh[ni]);
                    MMA_BF16(acc[mi][ni], afh[mi], bfl[ni]);
                    MMA_BF16(acc[mi][ni], afl[mi], bfh[ni]);
                }
        }
    };

    const int nch = K >> 6;
    if (AFP32) ldgA(0); else issueA(0, 0);
    issueB(0, 0);
    cpa_commit();

    for (int c = 0; c < nch; c++) {
        const int buf = c & 1;
        if (AFP32) stsA(buf);
        if (c + 1 < nch) {
            const int nb = (c + 1) & 1;
            if (!AFP32) issueA(c + 1, nb);
            issueB(c + 1, nb);
            cpa_commit();
            if (AFP32) ldgA(c + 1);
            cpa_wait1();
        } else {
            cpa_wait0();
        }
        __syncthreads();
        compute(buf);
        __syncthreads();
    }

    if (OUTM == 0) {
        float* C = Cf + (long)b * sCb + (long)h * sCh
                      + (long)blockIdx.y * 128 * ldc + blockIdx.x * 64;
        #pragma unroll
        for (int mi = 0; mi < 2; mi++) {
            int r0 = wm + mi * 16 + g;
            #pragma unroll
            for (int ni = 0; ni < 4; ni++) {
                int c0 = wn + ni * 8 + (t << 1);
                float bv0 = 0.f, bv1 = 0.f;
                if (bias) {
                    bv0 = bias[blockIdx.x * 64 + c0];
                    bv1 = bias[blockIdx.x * 64 + c0 + 1];
                }
                float2 v0, v1;
                v0.x = fmaf(acc[mi][ni][0], scale, bv0);
                v0.y = fmaf(acc[mi][ni][1], scale, bv1);
                v1.x = fmaf(acc[mi][ni][2], scale, bv0);
                v1.y = fmaf(acc[mi][ni][3], scale, bv1);
                *(float2*)(C + (long)r0 * ldc + c0) = v0;
                *(float2*)(C + (long)(r0 + 8) * ldc + c0) = v1;
            }
        }
    } else if (OUTM == 1) {
        u16* Ph = Cph + (long)b * sCb + (long)h * sCh
                      + (long)blockIdx.y * 128 * ldc + blockIdx.x * 64;
        u16* Pl = Cpl + (long)b * sCb + (long)h * sCh
                      + (long)blockIdx.y * 128 * ldc + blockIdx.x * 64;
        #pragma unroll
        for (int mi = 0; mi < 2; mi++) {
            int r0 = wm + mi * 16 + g;
            #pragma unroll
            for (int ni = 0; ni < 4; ni++) {
                int c0 = wn + ni * 8 + (t << 1);
                float bv0 = 0.f, bv1 = 0.f;
                if (bias) {
                    bv0 = bias[blockIdx.x * 64 + c0];
                    bv1 = bias[blockIdx.x * 64 + c0 + 1];
                }
                float v00 = fmaf(acc[mi][ni][0], scale, bv0);
                float v01 = fmaf(acc[mi][ni][1], scale, bv1);
                float v10 = fmaf(acc[mi][ni][2], scale, bv0);
                float v11 = fmaf(acc[mi][ni][3], scale, bv1);
                u16 h00, l00, h01, l01, h10, l10, h11, l11;
                split1(v00, h00, l00); split1(v01, h01, l01);
                split1(v10, h10, l10); split1(v11, h11, l11);
                *(u32*)(Ph + (long)r0 * ldc + c0)       = h00 | ((u32)h01 << 16);
                *(u32*)(Pl + (long)r0 * ldc + c0)       = l00 | ((u32)l01 << 16);
                *(u32*)(Ph + (long)(r0 + 8) * ldc + c0) = h10 | ((u32)h11 << 16);
                *(u32*)(Pl + (long)(r0 + 8) * ldc + c0) = l10 | ((u32)l11 << 16);
            }
        }
    } else {
        float* epi = (float*)dsm;
        #pragma unroll
        for (int mi = 0; mi < 2; mi++) {
            int r0 = wm + mi * 16 + g;
            #pragma unroll
            for (int ni = 0; ni < 4; ni++) {
                int c0 = wn + ni * 8 + (t << 1);
                epi[r0 * 65 + c0]           = acc[mi][ni][0];
                epi[r0 * 65 + c0 + 1]       = acc[mi][ni][1];
                epi[(r0 + 8) * 65 + c0]     = acc[mi][ni][2];
                epi[(r0 + 8) * 65 + c0 + 1] = acc[mi][ni][3];
            }
        }
        __syncthreads();
        long base = ((long)(blockIdx.y >> 4) * NH + blockIdx.x) * DK * SS
                  + (long)(blockIdx.y & 15) * 128;
        #pragma unroll
        for (int it = 0; it < 32; it++) {
            int i = it * 256 + tid;
            int n = i >> 7, m = i & 127;
            float v = epi[m * 65 + n] * scale;
            if (bias) v += bias[blockIdx.x * 64 + n];
            u16 hh, ll;
            split1(v, hh, ll);
            Cph[base + (long)n * SS + m] = hh;
            Cpl[base + (long)n * SS + m] = ll;
        }
    }
}

// ---------------- fused scores+softmax+PV (flash-style, attn written once) ----------------
// One CTA: 128 q-rows x one (b,h). 8 warps x 16 rows, each warp owns full 64-key width.
// Phase A: online (max,sum) over 32 key-chunks. Phase B: recompute S, write
// normalized P to attn, accumulate O += P@V with P hi/lo split in registers.
// A-fragment order is {a0,a1,a2,a3} = {(g,2t),(g+8,2t),(g,2t+8),(g+8,2t+8)} —
// i.e. tiles {2s:[01],[23], 2s+1:[01],[23]} packed IN THAT ORDER (no swap).
__global__ __launch_bounds__(256) void fused_attn(
    const u16* __restrict__ Qh, const u16* __restrict__ Ql,
    const u16* __restrict__ Kh, const u16* __restrict__ Kl,
    const u16* __restrict__ Vh, const u16* __restrict__ Vl,
    float* __restrict__ attn, u16* __restrict__ Cph, u16* __restrict__ Cpl)
{
    extern __shared__ char dsm[];
    const u32 sb = smem_u32(dsm);
    const int tid = threadIdx.x, lane = tid & 31, w = tid >> 5;
    const int wm = w << 4;                  // 16 rows per warp
    const int g = lane >> 2, t = lane & 3;
    const int z = blockIdx.z, b = z / NH, h = z % NH;
    const int q0 = blockIdx.y * 128;

    // smem: Q hi 0..16K, Q lo 16K..32K, K bufs 32768+buf*16384 (lo at +8192),
    //       V bufs 65536+buf*16384 (lo at +8192). total 96KB.
    {
        const u16* gqh = Qh + ((long)b * SS + q0) * DM + h * DK;
        const u16* gql = Ql + ((long)b * SS + q0) * DM + h * DK;
        #pragma unroll
        for (int it = 0; it < 4; it++) {
            int i = it * 256 + tid;
            int row = i >> 3, cc = i & 7;
            u32 so = SWZ((u32)(row * 128 + cc * 16));
            cpa16(sb + so,         gqh + (long)row * DM + cc * 8);
            cpa16(sb + 16384 + so, gql + (long)row * DM + cc * 8);
        }
    }

    const u32 a_base = (u32)((wm + (lane & 15)) * 128 + (lane >> 4) * 16);
    u32 b_base[4];
    #pragma unroll
    for (int np = 0; np < 4; np++) {
        int n = np * 16 + (lane & 7) + ((lane >> 4) << 3);
        b_base[np] = (u32)(n * 128 + ((lane >> 3) & 1) * 16);
    }

    auto issueK = [&](int c, int buf) {
        u32 kh = sb + 32768 + buf * 16384, kl = kh + 8192;
        const u16* gh = Kh + ((long)b * SS + c * 64) * DM + h * DK;
        const u16* gl = Kl + ((long)b * SS + c * 64) * DM + h * DK;
        #pragma unroll
        for (int it = 0; it < 2; it++) {
            int i = it * 256 + tid;
            int row = i >> 3, cc = i & 7;
            u32 so = SWZ((u32)(row * 128 + cc * 16));
            cpa16(kh + so, gh + (long)row * DM + cc * 8);
            cpa16(kl + so, gl + (long)row * DM + cc * 8);
        }
    };
    auto issueV = [&](int c, int buf) {
        u32 vh = sb + 65536 + buf * 16384, vl = vh + 8192;
        const u16* gh = Vh + ((long)(b * NH + h) * DK) * SS + c * 64;
        const u16* gl = Vl + ((long)(b * NH + h) * DK) * SS + c * 64;
        #pragma unroll
        for (int it = 0; it < 2; it++) {
            int i = it * 256 + tid;
            int row = i >> 3, cc = i & 7;
            u32 so = SWZ((u32)(row * 128 + cc * 16));
            cpa16(vh + so, gh + (long)row * SS + cc * 8);
            cpa16(vl + so, gl + (long)row * SS + cc * 8);
        }
    };

    float sacc[8][4];
    auto computeS = [&](int buf) {
        #pragma unroll
        for (int ni = 0; ni < 8; ni++)
            #pragma unroll
            for (int c4 = 0; c4 < 4; c4++) sacc[ni][c4] = 0.f;
        u32 kh = sb + 32768 + buf * 16384, kl = kh + 8192;
        #pragma unroll
        for (int s = 0; s < 4; s++) {
            u32 aH[4], aL[4];
            u32 o = SWZ(a_base + s * 32);
            ldsm4(sb + o,         aH[0], aH[1], aH[2], aH[3]);
            ldsm4(sb + 16384 + o, aL[0], aL[1], aL[2], aL[3]);
            u32 bh_[8][2], bl_[8][2];
            #pragma unroll
            for (int np = 0; np < 4; np++) {
                u32 ob = SWZ(b_base[np] + s * 32);
                u32 r0, r1, r2, r3;
                ldsm4(kh + ob, r0, r1, r2, r3);
                bh_[np * 2][0] = r0; bh_[np * 2][1] = r1;
                bh_[np * 2 + 1][0] = r2; bh_[np * 2 + 1][1] = r3;
                ldsm4(kl + ob, r0, r1, r2, r3);
                bl_[np * 2][0] = r0; bl_[np * 2][1] = r1;
                bl_[np * 2 + 1][0] = r2; bl_[np * 2 + 1][1] = r3;
            }
            #pragma unroll
            for (int ni = 0; ni < 8; ni++) {
                MMA_BF16(sacc[ni], aH, bh_[ni]);
                MMA_BF16(sacc[ni], aH, bl_[ni]);
                MMA_BF16(sacc[ni], aL, bh_[ni]);
            }
        }
    };

    // ---------------- Phase A: online row max + sum ----------------
    float mr0 = -1e30f, mr1 = -1e30f, sr0 = 0.f, sr1 = 0.f;
    issueK(0, 0);
    cpa_commit();
    for (int c = 0; c < SS / 64; c++) {
        const int buf = c & 1;
        if (c + 1 < SS / 64) { issueK(c + 1, buf ^ 1); cpa_commit(); cpa_wait1(); }
        else cpa_wait0();
        __syncthreads();
        computeS(buf);
        #pragma unroll
        for (int ni = 0; ni < 8; ni++)
            #pragma unroll
            for (int c4 = 0; c4 < 4; c4++) sacc[ni][c4] *= 0.125f;
        float lm0 = -1e30f, lm1 = -1e30f;
        #pragma unroll
        for (int ni = 0; ni < 8; ni++) {
            lm0 = fmaxf(lm0, fmaxf(sacc[ni][0], sacc[ni][1]));
            lm1 = fmaxf(lm1, fmaxf(sacc[ni][2], sacc[ni][3]));
        }
        lm0 = fmaxf(lm0, __shfl_xor_sync(0xffffffffu, lm0, 1));
        lm0 = fmaxf(lm0, __shfl_xor_sync(0xffffffffu, lm0, 2));
        lm1 = fmaxf(lm1, __shfl_xor_sync(0xffffffffu, lm1, 1));
        lm1 = fmaxf(lm1, __shfl_xor_sync(0xffffffffu, lm1, 2));
        float mn0 = fmaxf(mr0, lm0), mn1 = fmaxf(mr1, lm1);
        sr0 *= __expf(mr0 - mn0); sr1 *= __expf(mr1 - mn1);
        mr0 = mn0; mr1 = mn1;
        float s0 = 0.f, s1 = 0.f;
        #pragma unroll
        for (int ni = 0; ni < 8; ni++) {
            s0 += __expf(sacc[ni][0] - mr0) + __expf(sacc[ni][1] - mr0);
            s1 += __expf(sacc[ni][2] - mr1) + __expf(sacc[ni][3] - mr1);
        }
        s0 += __shfl_xor_sync(0xffffffffu, s0, 1);
        s0 += __shfl_xor_sync(0xffffffffu, s0, 2);
        s1 += __shfl_xor_sync(0xffffffffu, s1, 1);
        s1 += __shfl_xor_sync(0xffffffffu, s1, 2);
        sr0 += s0; sr1 += s1;
        __syncthreads();
    }
    const float is0 = 1.f / sr0, is1 = 1.f / sr1;

    // ---------------- Phase B: P write + O accumulation ----------------
    float oacc[8][4];
    #pragma unroll
    for (int nd = 0; nd < 8; nd++)
        #pragma unroll
        for (int c4 = 0; c4 < 4; c4++) oacc[nd][c4] = 0.f;

    float* attnB = attn + ((long)(b * NH + h) * SS + q0) * SS;
    issueK(0, 0); issueV(0, 0);
    cpa_commit();
    for (int c = 0; c < SS / 64; c++) {
        const int buf = c & 1;
        if (c + 1 < SS / 64) {
            issueK(c + 1, buf ^ 1); issueV(c + 1, buf ^ 1);
            cpa_commit(); cpa_wait1();
        } else cpa_wait0();
        __syncthreads();
        computeS(buf);
        const int r0 = wm + g, r1 = wm + 8 + g;
        #pragma unroll
        for (int ni = 0; ni < 8; ni++) {
            float p0 = __expf(fmaf(sacc[ni][0], 0.125f, -mr0)) * is0;
            float p1 = __expf(fmaf(sacc[ni][1], 0.125f, -mr0)) * is0;
            float p2 = __expf(fmaf(sacc[ni][2], 0.125f, -mr1)) * is1;
            float p3 = __expf(fmaf(sacc[ni][3], 0.125f, -mr1)) * is1;
            int col = c * 64 + ni * 8 + (t << 1);
            *(float2*)(attnB + (long)r0 * SS + col) = make_float2(p0, p1);
            *(float2*)(attnB + (long)r1 * SS + col) = make_float2(p2, p3);
            sacc[ni][0] = p0; sacc[ni][1] = p1; sacc[ni][2] = p2; sacc[ni][3] = p3;
        }
        u32 vh = sb + 65536 + buf * 16384, vl = vh + 8192;
        #pragma unroll
        for (int s = 0; s < 4; s++) {
            // A frags from P tiles ni=2s, 2s+1: order {2s[01], 2s[23], 2s+1[01], 2s+1[23]}
            u32 aH[4], aL[4];
            #pragma unroll
            for (int q = 0; q < 2; q++) {
                u16 ha, la, hb, lb;
                split1(sacc[2 * s + q][0], ha, la);
                split1(sacc[2 * s + q][1], hb, lb);
                aH[q * 2]     = ha | ((u32)hb << 16);
                aL[q * 2]     = la | ((u32)lb << 16);
                split1(sacc[2 * s + q][2], ha, la);
                split1(sacc[2 * s + q][3], hb, lb);
                aH[q * 2 + 1] = ha | ((u32)hb << 16);
                aL[q * 2 + 1] = la | ((u32)lb << 16);
            }
            u32 bvh[8][2], bvl[8][2];
            #pragma unroll
            for (int np = 0; np < 4; np++) {
                u32 ob = SWZ(b_base[np] + s * 32);
                u32 r0v, r1v, r2v, r3v;
                ldsm4(vh + ob, r0v, r1v, r2v, r3v);
                bvh[np * 2][0] = r0v; bvh[np * 2][1] = r1v;
                bvh[np * 2 + 1][0] = r2v; bvh[np * 2 + 1][1] = r3v;
                ldsm4(vl + ob, r0v, r1v, r2v, r3v);
                bvl[np * 2][0] = r0v; bvl[np * 2][1] = r1v;
                bvl[np * 2 + 1][0] = r2v; bvl[np * 2 + 1][1] = r3v;
            }
            #pragma unroll
            for (int nd = 0; nd < 8; nd++) {
                MMA_BF16(oacc[nd], aH, bvh[nd]);
                MMA_BF16(oacc[nd], aH, bvl[nd]);
                MMA_BF16(oacc[nd], aL, bvh[nd]);
            }
        }
        __syncthreads();
    }

    // ---- epilogue: ctx planes [b][s][h*64+d] ----
    u16* PhC = Cph + ((long)b * SS + q0) * DM + h * DK;
    u16* PlC = Cpl + ((long)b * SS + q0) * DM + h * DK;
    const int r0 = wm + g, r1 = wm + 8 + g;
    #pragma unroll
    for (int nd = 0; nd < 8; nd++) {
        int col = nd * 8 + (t << 1);
        u16 h0, l0, h1, l1;
        split1(oacc[nd][0], h0, l0); split1(oacc[nd][1], h1, l1);
        *(u32*)(PhC + (long)r0 * DM + col) = h0 | ((u32)h1 << 16);
        *(u32*)(PlC + (long)r0 * DM + col) = l0 | ((u32)l1 << 16);
        split1(oacc[nd][2], h0, l0); split1(oacc[nd][3], h1, l1);
        *(u32*)(PhC + (long)r1 * DM + col) = h0 | ((u32)h1 << 16);
        *(u32*)(PlC + (long)r1 * DM + col) = l0 | ((u32)l1 << 16);
    }
}

// ---------------- weight converter: fp32 -> bf16 hi/lo planes ----------------
__global__ __launch_bounds__(256) void splitw(const float* __restrict__ x,
                                              u16* __restrict__ ph, u16* __restrict__ pl)
{
    int i = (blockIdx.x * 256 + threadIdx.x) * 4;
    float4 v = *(const float4*)(x + i);
    u16 h0, l0, h1, l1, h2, l2, h3, l3;
    split1(v.x, h0, l0); split1(v.y, h1, l1);
    split1(v.z, h2, l2); split1(v.w, h3, l3);
    *(uint2*)(ph + i) = make_uint2(h0 | ((u32)h1 << 16), h2 | ((u32)h3 << 16));
    *(uint2*)(pl + i) = make_uint2(l0 | ((u32)l1 << 16), l2 | ((u32)l3 << 16));
}

extern "C" void kernel_launch(void* const* d_in, const int* in_sizes, int n_in,
                              void* d_out, int out_size)
{
    (void)in_sizes; (void)n_in; (void)out_size;

    const float* q  = (const float*)d_in[0];
    const float* k  = (const float*)d_in[1];
    const float* vv = (const float*)d_in[2];
    const float* Wq = (const float*)d_in[3];
    const float* bq = (const float*)d_in[4];
    const float* Wk = (const float*)d_in[5];
    const float* bk = (const float*)d_in[6];
    const float* Wv = (const float*)d_in[7];
    const float* bv = (const float*)d_in[8];
    const float* Wo = (const float*)d_in[9];
    const float* bo = (const float*)d_in[10];

    float* out  = (float*)d_out;                 // [B,S,D]
    float* attn = out + (long)BB * SS * DM;      // [B,H,S,S]

    u16 *Qh, *Ql, *Kh, *Kl, *Vth, *Vtl, *Ch, *Cl, *Wh, *Wl;
    cudaGetSymbolAddress((void**)&Qh,  g_Qh);  cudaGetSymbolAddress((void**)&Ql,  g_Ql);
    cudaGetSymbolAddress((void**)&Kh,  g_Kh);  cudaGetSymbolAddress((void**)&Kl,  g_Kl);
    cudaGetSymbolAddress((void**)&Vth, g_Vth); cudaGetSymbolAddress((void**)&Vtl, g_Vtl);
    cudaGetSymbolAddress((void**)&Ch,  g_Ch);  cudaGetSymbolAddress((void**)&Cl,  g_Cl);
    cudaGetSymbolAddress((void**)&Wh,  g_Wh);  cudaGetSymbolAddress((void**)&Wl,  g_Wl);

    const int shm = 98304;
    cudaFuncSetAttribute(gemm_p<0,0>, cudaFuncAttributeMaxDynamicSharedMemorySize, shm);
    cudaFuncSetAttribute(gemm_p<1,1>, cudaFuncAttributeMaxDynamicSharedMemorySize, shm);
    cudaFuncSetAttribute(gemm_p<1,2>, cudaFuncAttributeMaxDynamicSharedMemorySize, shm);
    cudaFuncSetAttribute(fused_attn,  cudaFuncAttributeMaxDynamicSharedMemorySize, shm);

    dim3 blk(256);

    splitw<<<DM * DM / 1024, blk>>>(Wq, Wh + 0 * DM * DM, Wl + 0 * DM * DM);
    splitw<<<DM * DM / 1024, blk>>>(Wk, Wh + 1 * DM * DM, Wl + 1 * DM * DM);
    splitw<<<DM * DM / 1024, blk>>>(Wv, Wh + 2 * DM * DM, Wl + 2 * DM * DM);
    splitw<<<DM * DM / 1024, blk>>>(Wo, Wh + 3 * DM * DM, Wl + 3 * DM * DM);

    dim3 gproj(DM / 64, (BB * SS) / 128, 1);

    gemm_p<1,1><<<gproj, blk, shm>>>(q, nullptr, nullptr, DM, 0, 0,
                                     Wh + 0 * DM * DM, Wl + 0 * DM * DM, DM, 0, 0,
                                     nullptr, Qh, Ql, DM, 0, 0, DM, 1.f, bq);
    gemm_p<1,1><<<gproj, blk, shm>>>(k, nullptr, nullptr, DM, 0, 0,
                                     Wh + 1 * DM * DM, Wl + 1 * DM * DM, DM, 0, 0,
                                     nullptr, Kh, Kl, DM, 0, 0, DM, 1.f, bk);
    gemm_p<1,2><<<gproj, blk, shm>>>(vv, nullptr, nullptr, DM, 0, 0,
                                     Wh + 2 * DM * DM, Wl + 2 * DM * DM, DM, 0, 0,
                                     nullptr, Vth, Vtl, 0, 0, 0, DM, 1.f, bv);

    // fused scores + softmax + PV (attn written exactly once)
    fused_attn<<<dim3(1, SS / 128, BB * NH), blk, shm>>>(
        Qh, Ql, Kh, Kl, Vth, Vtl, attn, Ch, Cl);

    // output projection: out = ctx @ Wo^T + bo
    gemm_p<0,0><<<gproj, blk, shm>>>(nullptr, Ch, Cl, DM, 0, 0,
                                     Wh + 3 * DM * DM, Wl + 3 * DM * DM, DM, 0, 0,
                                     out, nullptr, nullptr, DM, 0, 0,
                                     DM, 1.f, bo);
}

// round 14
// speedup vs baseline: 1.3741x; 1.0891x over previous
#include <cuda_runtime.h>
#include <cuda_bf16.h>
#include <cstdint>

#define BB 2
#define SS 2048
#define DM 1024
#define NH 16
#define DK 64

typedef unsigned short u16;
typedef unsigned int   u32;

// ---- bf16 hi/lo plane scratch (device globals; no allocation APIs) ----
static __device__ u16 g_Qh [BB*SS*DM], g_Ql [BB*SS*DM];
static __device__ u16 g_Kh [BB*SS*DM], g_Kl [BB*SS*DM];
static __device__ u16 g_Vth[BB*SS*DM], g_Vtl[BB*SS*DM];   // [b][h][dk][s]
static __device__ u16 g_Ch [BB*SS*DM], g_Cl [BB*SS*DM];
static __device__ u16 g_Wh [4*DM*DM],  g_Wl [4*DM*DM];

// ---------------- helpers ----------------
__device__ __forceinline__ u32 smem_u32(const void* p) {
    u32 a;
    asm("{ .reg .u64 t; cvta.to.shared.u64 t, %1; cvt.u32.u64 %0, t; }"
        : "=r"(a) : "l"(p));
    return a;
}
#define SWZ(o) ((o) ^ (((o) >> 3) & 0x70))

__device__ __forceinline__ void split1(float v, u16& h, u16& l) {
    __nv_bfloat16 hb = __float2bfloat16(v);
    h = __bfloat16_as_ushort(hb);
    l = __bfloat16_as_ushort(__float2bfloat16(v - __bfloat162float(hb)));
}

__device__ __forceinline__ void cpa16(u32 s, const void* g) {
    asm volatile("cp.async.cg.shared.global [%0], [%1], 16;" :: "r"(s), "l"(g));
}
__device__ __forceinline__ void cpa_commit() {
    asm volatile("cp.async.commit_group;" ::: "memory");
}
__device__ __forceinline__ void cpa_wait1() {
    asm volatile("cp.async.wait_group 1;" ::: "memory");
}
__device__ __forceinline__ void cpa_wait0() {
    asm volatile("cp.async.wait_group 0;" ::: "memory");
}
__device__ __forceinline__ void ldsm4(u32 a, u32& r0, u32& r1, u32& r2, u32& r3) {
    asm volatile("ldmatrix.sync.aligned.m8n8.x4.shared.b16 {%0,%1,%2,%3}, [%4];"
        : "=r"(r0), "=r"(r1), "=r"(r2), "=r"(r3) : "r"(a));
}

#define MMA_BF16(acc, af, bf)                                                   \
    asm volatile(                                                               \
        "mma.sync.aligned.m16n8k16.row.col.f32.bf16.bf16.f32 "                  \
        "{%0,%1,%2,%3}, {%4,%5,%6,%7}, {%8,%9}, {%0,%1,%2,%3};"                 \
        : "+f"(acc[0]), "+f"(acc[1]), "+f"(acc[2]), "+f"(acc[3])                \
        : "r"(af[0]), "r"(af[1]), "r"(af[2]), "r"(af[3]), "r"(bf[0]), "r"(bf[1]))

// ---------------- big-tile GEMM: C[128x128] = A * B^T (NT), bf16x2 3-term ---------
// CTA 128x128, 8 warps (4m x 2n), warp tile 32x64. BK=32, hi/lo planes PACKED in one
// 128B swizzled row (bytes 0-63 hi, 64-127 lo) -> 48 MMA : 12 LDSM per warp k16-step.
// AFP32=1: A fp32 gmem split in-kernel. AFP32=0: A pre-split planes via cp.async.
// B always planes via cp.async. SEL2: blockIdx.z==1 selects the 2nd operand set
// (merged Q/K projections). OUTM: 0=fp32 C + bias; 1=bf16 planes + bias;
// 2=V^T per head planes + bias (smem-staged transpose).
template <int AFP32, int OUTM, int SEL2>
__global__ __launch_bounds__(256, 2) void gemm_big(
    const float* __restrict__ Af,  const float* __restrict__ Af2,
    const u16* __restrict__ Aph, const u16* __restrict__ Apl,
    const u16* __restrict__ Bph, const u16* __restrict__ Bpl,
    const u16* __restrict__ B2ph, const u16* __restrict__ B2pl,
    float* __restrict__ Cf, u16* __restrict__ Cph, u16* __restrict__ Cpl,
    u16* __restrict__ C2ph, u16* __restrict__ C2pl,
    const float* __restrict__ bias, const float* __restrict__ bias2,
    int lda, int ldb, int ldc, int K)
{
    extern __shared__ char dsm[];
    const u32 sbase = smem_u32(dsm);
    const int tid = threadIdx.x, lane = tid & 31, w = tid >> 5;
    const int wm = (w & 3) << 5;      // warp m offset: 0,32,64,96
    const int wn = (w >> 2) << 6;     // warp n offset: 0,64
    const int g = lane >> 2, t = lane & 3;

    const float* A_f = Af;
    const u16 *AhG = Aph, *AlG = Apl;
    const u16 *BhG = Bph, *BlG = Bpl;
    u16 *COh = Cph, *COl = Cpl;
    const float* bi = bias;
    if (SEL2 && blockIdx.z == 1) {
        A_f = Af2; BhG = B2ph; BlG = B2pl; COh = C2ph; COl = C2pl; bi = bias2;
    }
    const long arow0 = (long)blockIdx.y * 128;
    if (AFP32) { if (A_f) A_f += arow0 * lda; }
    else       { AhG += arow0 * lda; AlG += arow0 * lda; }
    BhG += (long)blockIdx.x * 128 * ldb;
    BlG += (long)blockIdx.x * 128 * ldb;

    // smem: A bufs at 0 / 16384 ; B bufs at 32768 / 49152 (16KB each)
    float acc[2][8][4];
    #pragma unroll
    for (int i = 0; i < 2; i++)
        #pragma unroll
        for (int j = 0; j < 8; j++)
            #pragma unroll
            for (int c = 0; c < 4; c++) acc[i][j][c] = 0.f;

    u32 a_base[2], b_base[4];
    #pragma unroll
    for (int mi = 0; mi < 2; mi++)
        a_base[mi] = (u32)((wm + mi * 16 + (lane & 15)) * 128 + (lane >> 4) * 16);
    #pragma unroll
    for (int np = 0; np < 4; np++)
        b_base[np] = (u32)((wn + np * 16 + (lane & 7) + ((lane >> 4) << 3)) * 128
                           + ((lane >> 3) & 1) * 16);

    // cp.async fill for a 128-row plane pair into packed rows
    auto issueP = [&](const u16* gh, const u16* gl, int ld, int c, u32 dst) {
        #pragma unroll
        for (int it = 0; it < 4; it++) {
            int i = it * 256 + tid;
            int row = i >> 3, seg = i & 7;
            if (seg < 4) {
                cpa16(dst + SWZ((u32)(row * 128 + seg * 16)),
                      gh + (long)row * ld + c * 32 + seg * 8);
            } else {
                cpa16(dst + SWZ((u32)(row * 128 + 64 + (seg - 4) * 16)),
                      gl + (long)row * ld + c * 32 + (seg - 4) * 8);
            }
        }
    };

    float4 ra[4];
    auto ldgA = [&](int c) {
        #pragma unroll
        for (int it = 0; it < 4; it++) {
            int i = it * 256 + tid;
            int row = i >> 3, cq = (i & 7) << 2;
            ra[it] = *(const float4*)(A_f + (long)row * lda + c * 32 + cq);
        }
    };
    auto stsA = [&](int buf) {
        char* ap = dsm + buf * 16384;
        #pragma unroll
        for (int it = 0; it < 4; it++) {
            int i = it * 256 + tid;
            int row = i >> 3, cq = (i & 7) << 2;
            u16 h0, l0, h1, l1, h2, l2, h3, l3;
            split1(ra[it].x, h0, l0); split1(ra[it].y, h1, l1);
            split1(ra[it].z, h2, l2); split1(ra[it].w, h3, l3);
            *(uint2*)(ap + SWZ((u32)(row * 128 + cq * 2)))
                = make_uint2(h0 | ((u32)h1 << 16), h2 | ((u32)h3 << 16));
            *(uint2*)(ap + SWZ((u32)(row * 128 + 64 + cq * 2)))
                = make_uint2(l0 | ((u32)l1 << 16), l2 | ((u32)l3 << 16));
        }
    };

    auto compute = [&](int buf) {
        u32 ab = sbase + buf * 16384;
        u32 bb = sbase + 32768 + buf * 16384;
        #pragma unroll
        for (int s = 0; s < 2; s++) {
            u32 aH[2][4], aL[2][4];
            #pragma unroll
            for (int mi = 0; mi < 2; mi++) {
                ldsm4(ab + SWZ(a_base[mi] + s * 32),
                      aH[mi][0], aH[mi][1], aH[mi][2], aH[mi][3]);
                ldsm4(ab + SWZ(a_base[mi] + s * 32 + 64),
                      aL[mi][0], aL[mi][1], aL[mi][2], aL[mi][3]);
            }
            #pragma unroll
            for (int np = 0; np < 4; np++) {
                u32 h0, h1, h2, h3, l0, l1, l2, l3;
                ldsm4(bb + SWZ(b_base[np] + s * 32), h0, h1, h2, h3);
                ldsm4(bb + SWZ(b_base[np] + s * 32 + 64), l0, l1, l2, l3);
                u32 bfh[2][2] = {{h0, h1}, {h2, h3}};
                u32 bfl[2][2] = {{l0, l1}, {l2, l3}};
                #pragma unroll
                for (int mi = 0; mi < 2; mi++)
                    #pragma unroll
                    for (int sub = 0; sub < 2; sub++) {
                        int ni = np * 2 + sub;
                        MMA_BF16(acc[mi][ni], aH[mi], bfh[sub]);
                        MMA_BF16(acc[mi][ni], aH[mi], bfl[sub]);
                        MMA_BF16(acc[mi][ni], aL[mi], bfh[sub]);
                    }
            }
        }
    };

    const int nch = K >> 5;
    if (AFP32) ldgA(0); else issueP(AhG, AlG, lda, 0, sbase);
    issueP(BhG, BlG, ldb, 0, sbase + 32768);
    cpa_commit();

    for (int c = 0; c < nch; c++) {
        const int buf = c & 1;
        if (AFP32) stsA(buf);
        if (c + 1 < nch) {
            const int nb = buf ^ 1;
            if (!AFP32) issueP(AhG, AlG, lda, c + 1, sbase + nb * 16384);
            issueP(BhG, BlG, ldb, c + 1, sbase + 32768 + nb * 16384);
            cpa_commit();
            if (AFP32) ldgA(c + 1);
            cpa_wait1();
        } else {
            cpa_wait0();
        }
        __syncthreads();
        compute(buf);
        __syncthreads();
    }

    // ---------------- epilogues ----------------
    if (OUTM == 0) {
        float* C = Cf + arow0 * ldc + blockIdx.x * 128;
        #pragma unroll
        for (int mi = 0; mi < 2; mi++) {
            int r0 = wm + mi * 16 + g;
            #pragma unroll
            for (int ni = 0; ni < 8; ni++) {
                int c0 = wn + ni * 8 + (t << 1);
                float bv0 = bi[blockIdx.x * 128 + c0];
                float bv1 = bi[blockIdx.x * 128 + c0 + 1];
                *(float2*)(C + (long)r0 * ldc + c0)
                    = make_float2(acc[mi][ni][0] + bv0, acc[mi][ni][1] + bv1);
                *(float2*)(C + (long)(r0 + 8) * ldc + c0)
                    = make_float2(acc[mi][ni][2] + bv0, acc[mi][ni][3] + bv1);
            }
        }
    } else if (OUTM == 1) {
        u16* Ph = COh + arow0 * ldc + blockIdx.x * 128;
        u16* Pl = COl + arow0 * ldc + blockIdx.x * 128;
        #pragma unroll
        for (int mi = 0; mi < 2; mi++) {
            int r0 = wm + mi * 16 + g;
            #pragma unroll
            for (int ni = 0; ni < 8; ni++) {
                int c0 = wn + ni * 8 + (t << 1);
                float bv0 = bi[blockIdx.x * 128 + c0];
                float bv1 = bi[blockIdx.x * 128 + c0 + 1];
                float v00 = acc[mi][ni][0] + bv0, v01 = acc[mi][ni][1] + bv1;
                float v10 = acc[mi][ni][2] + bv0, v11 = acc[mi][ni][3] + bv1;
                u16 h00, l00, h01, l01, h10, l10, h11, l11;
                split1(v00, h00, l00); split1(v01, h01, l01);
                split1(v10, h10, l10); split1(v11, h11, l11);
                *(u32*)(Ph + (long)r0 * ldc + c0)       = h00 | ((u32)h01 << 16);
                *(u32*)(Pl + (long)r0 * ldc + c0)       = l00 | ((u32)l01 << 16);
                *(u32*)(Ph + (long)(r0 + 8) * ldc + c0) = h10 | ((u32)h11 << 16);
                *(u32*)(Pl + (long)(r0 + 8) * ldc + c0) = l10 | ((u32)l11 << 16);
            }
        }
    } else {
        // OUTM==2: V^T per head. Stage acc in smem then coalesced transpose-write.
        float* epi = (float*)dsm;
        #pragma unroll
        for (int mi = 0; mi < 2; mi++) {
            int r0 = wm + mi * 16 + g;
            #pragma unroll
            for (int ni = 0; ni < 8; ni++) {
                int c0 = wn + ni * 8 + (t << 1);
                epi[r0 * 129 + c0]           = acc[mi][ni][0];
                epi[r0 * 129 + c0 + 1]       = acc[mi][ni][1];
                epi[(r0 + 8) * 129 + c0]     = acc[mi][ni][2];
                epi[(r0 + 8) * 129 + c0 + 1] = acc[mi][ni][3];
            }
        }
        __syncthreads();
        #pragma unroll
        for (int it = 0; it < 64; it++) {
            int i = it * 256 + tid;
            int n = i >> 7, m = i & 127;
            float v = epi[m * 129 + n] + bi[blockIdx.x * 128 + n];
            int h = (blockIdx.x << 1) + (n >> 6), dk = n & 63;
            long grow = arow0 + m;
            long b = grow >> 11, s = grow & 2047;
            long addr = ((b * NH + h) * (long)DK + dk) * SS + s;
            u16 hh, ll;
            split1(v, hh, ll);
            COh[addr] = hh;
            COl[addr] = ll;
        }
    }
}

// ---------------- fused scores+softmax+PV (verbatim from round 13; proven) ----------
__global__ __launch_bounds__(256) void fused_attn(
    const u16* __restrict__ Qh, const u16* __restrict__ Ql,
    const u16* __restrict__ Kh, const u16* __restrict__ Kl,
    const u16* __restrict__ Vh, const u16* __restrict__ Vl,
    float* __restrict__ attn, u16* __restrict__ Cph, u16* __restrict__ Cpl)
{
    extern __shared__ char dsm[];
    const u32 sb = smem_u32(dsm);
    const int tid = threadIdx.x, lane = tid & 31, w = tid >> 5;
    const int wm = w << 4;                  // 16 rows per warp
    const int g = lane >> 2, t = lane & 3;
    const int z = blockIdx.z, b = z / NH, h = z % NH;
    const int q0 = blockIdx.y * 128;

    {
        const u16* gqh = Qh + ((long)b * SS + q0) * DM + h * DK;
        const u16* gql = Ql + ((long)b * SS + q0) * DM + h * DK;
        #pragma unroll
        for (int it = 0; it < 4; it++) {
            int i = it * 256 + tid;
            int row = i >> 3, cc = i & 7;
            u32 so = SWZ((u32)(row * 128 + cc * 16));
            cpa16(sb + so,         gqh + (long)row * DM + cc * 8);
            cpa16(sb + 16384 + so, gql + (long)row * DM + cc * 8);
        }
    }

    const u32 a_base = (u32)((wm + (lane & 15)) * 128 + (lane >> 4) * 16);
    u32 b_base[4];
    #pragma unroll
    for (int np = 0; np < 4; np++) {
        int n = np * 16 + (lane & 7) + ((lane >> 4) << 3);
        b_base[np] = (u32)(n * 128 + ((lane >> 3) & 1) * 16);
    }

    auto issueK = [&](int c, int buf) {
        u32 kh = sb + 32768 + buf * 16384, kl = kh + 8192;
        const u16* gh = Kh + ((long)b * SS + c * 64) * DM + h * DK;
        const u16* gl = Kl + ((long)b * SS + c * 64) * DM + h * DK;
        #pragma unroll
        for (int it = 0; it < 2; it++) {
            int i = it * 256 + tid;
            int row = i >> 3, cc = i & 7;
            u32 so = SWZ((u32)(row * 128 + cc * 16));
            cpa16(kh + so, gh + (long)row * DM + cc * 8);
            cpa16(kl + so, gl + (long)row * DM + cc * 8);
        }
    };
    auto issueV = [&](int c, int buf) {
        u32 vh = sb + 65536 + buf * 16384, vl = vh + 8192;
        const u16* gh = Vh + ((long)(b * NH + h) * DK) * SS + c * 64;
        const u16* gl = Vl + ((long)(b * NH + h) * DK) * SS + c * 64;
        #pragma unroll
        for (int it = 0; it < 2; it++) {
            int i = it * 256 + tid;
            int row = i >> 3, cc = i & 7;
            u32 so = SWZ((u32)(row * 128 + cc * 16));
            cpa16(vh + so, gh + (long)row * SS + cc * 8);
            cpa16(vl + so, gl + (long)row * SS + cc * 8);
        }
    };

    float sacc[8][4];
    auto computeS = [&](int buf) {
        #pragma unroll
        for (int ni = 0; ni < 8; ni++)
            #pragma unroll
            for (int c4 = 0; c4 < 4; c4++) sacc[ni][c4] = 0.f;
        u32 kh = sb + 32768 + buf * 16384, kl = kh + 8192;
        #pragma unroll
        for (int s = 0; s < 4; s++) {
            u32 aH[4], aL[4];
            u32 o = SWZ(a_base + s * 32);
            ldsm4(sb + o,         aH[0], aH[1], aH[2], aH[3]);
            ldsm4(sb + 16384 + o, aL[0], aL[1], aL[2], aL[3]);
            u32 bh_[8][2], bl_[8][2];
            #pragma unroll
            for (int np = 0; np < 4; np++) {
                u32 ob = SWZ(b_base[np] + s * 32);
                u32 r0, r1, r2, r3;
                ldsm4(kh + ob, r0, r1, r2, r3);
                bh_[np * 2][0] = r0; bh_[np * 2][1] = r1;
                bh_[np * 2 + 1][0] = r2; bh_[np * 2 + 1][1] = r3;
                ldsm4(kl + ob, r0, r1, r2, r3);
                bl_[np * 2][0] = r0; bl_[np * 2][1] = r1;
                bl_[np * 2 + 1][0] = r2; bl_[np * 2 + 1][1] = r3;
            }
            #pragma unroll
            for (int ni = 0; ni < 8; ni++) {
                MMA_BF16(sacc[ni], aH, bh_[ni]);
                MMA_BF16(sacc[ni], aH, bl_[ni]);
                MMA_BF16(sacc[ni], aL, bh_[ni]);
            }
        }
    };

    // Phase A: online row max + sum
    float mr0 = -1e30f, mr1 = -1e30f, sr0 = 0.f, sr1 = 0.f;
    issueK(0, 0);
    cpa_commit();
    for (int c = 0; c < SS / 64; c++) {
        const int buf = c & 1;
        if (c + 1 < SS / 64) { issueK(c + 1, buf ^ 1); cpa_commit(); cpa_wait1(); }
        else cpa_wait0();
        __syncthreads();
        computeS(buf);
        #pragma unroll
        for (int ni = 0; ni < 8; ni++)
            #pragma unroll
            for (int c4 = 0; c4 < 4; c4++) sacc[ni][c4] *= 0.125f;
        float lm0 = -1e30f, lm1 = -1e30f;
        #pragma unroll
        for (int ni = 0; ni < 8; ni++) {
            lm0 = fmaxf(lm0, fmaxf(sacc[ni][0], sacc[ni][1]));
            lm1 = fmaxf(lm1, fmaxf(sacc[ni][2], sacc[ni][3]));
        }
        lm0 = fmaxf(lm0, __shfl_xor_sync(0xffffffffu, lm0, 1));
        lm0 = fmaxf(lm0, __shfl_xor_sync(0xffffffffu, lm0, 2));
        lm1 = fmaxf(lm1, __shfl_xor_sync(0xffffffffu, lm1, 1));
        lm1 = fmaxf(lm1, __shfl_xor_sync(0xffffffffu, lm1, 2));
        float mn0 = fmaxf(mr0, lm0), mn1 = fmaxf(mr1, lm1);
        sr0 *= __expf(mr0 - mn0); sr1 *= __expf(mr1 - mn1);
        mr0 = mn0; mr1 = mn1;
        float s0 = 0.f, s1 = 0.f;
        #pragma unroll
        for (int ni = 0; ni < 8; ni++) {
            s0 += __expf(sacc[ni][0] - mr0) + __expf(sacc[ni][1] - mr0);
            s1 += __expf(sacc[ni][2] - mr1) + __expf(sacc[ni][3] - mr1);
        }
        s0 += __shfl_xor_sync(0xffffffffu, s0, 1);
        s0 += __shfl_xor_sync(0xffffffffu, s0, 2);
        s1 += __shfl_xor_sync(0xffffffffu, s1, 1);
        s1 += __shfl_xor_sync(0xffffffffu, s1, 2);
        sr0 += s0; sr1 += s1;
        __syncthreads();
    }
    const float is0 = 1.f / sr0, is1 = 1.f / sr1;

    // Phase B: P write + O accumulation
    float oacc[8][4];
    #pragma unroll
    for (int nd = 0; nd < 8; nd++)
        #pragma unroll
        for (int c4 = 0; c4 < 4; c4++) oacc[nd][c4] = 0.f;

    float* attnB = attn + ((long)(b * NH + h) * SS + q0) * SS;
    issueK(0, 0); issueV(0, 0);
    cpa_commit();
    for (int c = 0; c < SS / 64; c++) {
        const int buf = c & 1;
        if (c + 1 < SS / 64) {
            issueK(c + 1, buf ^ 1); issueV(c + 1, buf ^ 1);
            cpa_commit(); cpa_wait1();
        } else cpa_wait0();
        __syncthreads();
        computeS(buf);
        const int r0 = wm + g, r1 = wm + 8 + g;
        #pragma unroll
        for (int ni = 0; ni < 8; ni++) {
            float p0 = __expf(fmaf(sacc[ni][0], 0.125f, -mr0)) * is0;
            float p1 = __expf(fmaf(sacc[ni][1], 0.125f, -mr0)) * is0;
            float p2 = __expf(fmaf(sacc[ni][2], 0.125f, -mr1)) * is1;
            float p3 = __expf(fmaf(sacc[ni][3], 0.125f, -mr1)) * is1;
            int col = c * 64 + ni * 8 + (t << 1);
            *(float2*)(attnB + (long)r0 * SS + col) = make_float2(p0, p1);
            *(float2*)(attnB + (long)r1 * SS + col) = make_float2(p2, p3);
            sacc[ni][0] = p0; sacc[ni][1] = p1; sacc[ni][2] = p2; sacc[ni][3] = p3;
        }
        u32 vh = sb + 65536 + buf * 16384, vl = vh + 8192;
        #pragma unroll
        for (int s = 0; s < 4; s++) {
            u32 aH[4], aL[4];
            #pragma unroll
            for (int q = 0; q < 2; q++) {
                u16 ha, la, hb, lb;
                split1(sacc[2 * s + q][0], ha, la);
                split1(sacc[2 * s + q][1], hb, lb);
                aH[q * 2]     = ha | ((u32)hb << 16);
                aL[q * 2]     = la | ((u32)lb << 16);
                split1(sacc[2 * s + q][2], ha, la);
                split1(sacc[2 * s + q][3], hb, lb);
                aH[q * 2 + 1] = ha | ((u32)hb << 16);
                aL[q * 2 + 1] = la | ((u32)lb << 16);
            }
            u32 bvh[8][2], bvl[8][2];
            #pragma unroll
            for (int np = 0; np < 4; np++) {
                u32 ob = SWZ(b_base[np] + s * 32);
                u32 r0v, r1v, r2v, r3v;
                ldsm4(vh + ob, r0v, r1v, r2v, r3v);
                bvh[np * 2][0] = r0v; bvh[np * 2][1] = r1v;
                bvh[np * 2 + 1][0] = r2v; bvh[np * 2 + 1][1] = r3v;
                ldsm4(vl + ob, r0v, r1v, r2v, r3v);
                bvl[np * 2][0] = r0v; bvl[np * 2][1] = r1v;
                bvl[np * 2 + 1][0] = r2v; bvl[np * 2 + 1][1] = r3v;
            }
            #pragma unroll
            for (int nd = 0; nd < 8; nd++) {
                MMA_BF16(oacc[nd], aH, bvh[nd]);
                MMA_BF16(oacc[nd], aH, bvl[nd]);
                MMA_BF16(oacc[nd], aL, bvh[nd]);
            }
        }
        __syncthreads();
    }

    u16* PhC = Cph + ((long)b * SS + q0) * DM + h * DK;
    u16* PlC = Cpl + ((long)b * SS + q0) * DM + h * DK;
    const int r0 = wm + g, r1 = wm + 8 + g;
    #pragma unroll
    for (int nd = 0; nd < 8; nd++) {
        int col = nd * 8 + (t << 1);
        u16 h0, l0, h1, l1;
        split1(oacc[nd][0], h0, l0); split1(oacc[nd][1], h1, l1);
        *(u32*)(PhC + (long)r0 * DM + col) = h0 | ((u32)h1 << 16);
        *(u32*)(PlC + (long)r0 * DM + col) = l0 | ((u32)l1 << 16);
        split1(oacc[nd][2], h0, l0); split1(oacc[nd][3], h1, l1);
        *(u32*)(PhC + (long)r1 * DM + col) = h0 | ((u32)h1 << 16);
        *(u32*)(PlC + (long)r1 * DM + col) = l0 | ((u32)l1 << 16);
    }
}

// ---------------- weight converter: 4 weights -> bf16 hi/lo planes, ONE launch ------
__global__ __launch_bounds__(256) void splitw4(
    const float* __restrict__ w0, const float* __restrict__ w1,
    const float* __restrict__ w2, const float* __restrict__ w3,
    u16* __restrict__ ph, u16* __restrict__ pl)
{
    long i = ((long)blockIdx.x * 256 + threadIdx.x) * 4;  // [0, 4*DM*DM)
    int sel = (int)(i >> 20);
    const float* src = (sel == 0) ? w0 : (sel == 1) ? w1 : (sel == 2) ? w2 : w3;
    long j = i & (DM * DM - 1);
    float4 v = *(const float4*)(src + j);
    u16 h0, l0, h1, l1, h2, l2, h3, l3;
    split1(v.x, h0, l0); split1(v.y, h1, l1);
    split1(v.z, h2, l2); split1(v.w, h3, l3);
    *(uint2*)(ph + i) = make_uint2(h0 | ((u32)h1 << 16), h2 | ((u32)h3 << 16));
    *(uint2*)(pl + i) = make_uint2(l0 | ((u32)l1 << 16), l2 | ((u32)l3 << 16));
}

extern "C" void kernel_launch(void* const* d_in, const int* in_sizes, int n_in,
                              void* d_out, int out_size)
{
    (void)in_sizes; (void)n_in; (void)out_size;

    const float* q  = (const float*)d_in[0];
    const float* k  = (const float*)d_in[1];
    const float* vv = (const float*)d_in[2];
    const float* Wq = (const float*)d_in[3];
    const float* bq = (const float*)d_in[4];
    const float* Wk = (const float*)d_in[5];
    const float* bk = (const float*)d_in[6];
    const float* Wv = (const float*)d_in[7];
    const float* bv = (const float*)d_in[8];
    const float* Wo = (const float*)d_in[9];
    const float* bo = (const float*)d_in[10];

    float* out  = (float*)d_out;                 // [B,S,D]
    float* attn = out + (long)BB * SS * DM;      // [B,H,S,S]

    u16 *Qh, *Ql, *Kh, *Kl, *Vth, *Vtl, *Ch, *Cl, *Wh, *Wl;
    cudaGetSymbolAddress((void**)&Qh,  g_Qh);  cudaGetSymbolAddress((void**)&Ql,  g_Ql);
    cudaGetSymbolAddress((void**)&Kh,  g_Kh);  cudaGetSymbolAddress((void**)&Kl,  g_Kl);
    cudaGetSymbolAddress((void**)&Vth, g_Vth); cudaGetSymbolAddress((void**)&Vtl, g_Vtl);
    cudaGetSymbolAddress((void**)&Ch,  g_Ch);  cudaGetSymbolAddress((void**)&Cl,  g_Cl);
    cudaGetSymbolAddress((void**)&Wh,  g_Wh);  cudaGetSymbolAddress((void**)&Wl,  g_Wl);

    const int shm_big = 66048;   // 64KB operands; 66048 covers OUTM=2 epi staging
    const int shm_f   = 98304;
    cudaFuncSetAttribute(gemm_big<1,1,1>, cudaFuncAttributeMaxDynamicSharedMemorySize, shm_big);
    cudaFuncSetAttribute(gemm_big<1,2,0>, cudaFuncAttributeMaxDynamicSharedMemorySize, shm_big);
    cudaFuncSetAttribute(gemm_big<0,0,0>, cudaFuncAttributeMaxDynamicSharedMemorySize, shm_big);
    cudaFuncSetAttribute(fused_attn,      cudaFuncAttributeMaxDynamicSharedMemorySize, shm_f);

    dim3 blk(256);
    const int M1 = DM * DM;

    // launch 0: all weight planes
    splitw4<<<4 * M1 / 1024, blk>>>(Wq, Wk, Wv, Wo, Wh, Wl);

    // launch 1: Q and K projections merged (z selects operand set)
    gemm_big<1,1,1><<<dim3(DM / 128, (BB * SS) / 128, 2), blk, shm_big>>>(
        q, k, nullptr, nullptr,
        Wh + 0 * M1, Wl + 0 * M1, Wh + 1 * M1, Wl + 1 * M1,
        nullptr, Qh, Ql, Kh, Kl,
        bq, bk, DM, DM, DM, DM);

    // launch 2: V projection -> V^T planes per head
    gemm_big<1,2,0><<<dim3(DM / 128, (BB * SS) / 128, 1), blk, shm_big>>>(
        vv, nullptr, nullptr, nullptr,
        Wh + 2 * M1, Wl + 2 * M1, nullptr, nullptr,
        nullptr, Vth, Vtl, nullptr, nullptr,
        bv, nullptr, DM, DM, 0, DM);

    // launch 3 (ncu-captured): fused scores + softmax + PV (attn written once)
    fused_attn<<<dim3(1, SS / 128, BB * NH), blk, shm_f>>>(
        Qh, Ql, Kh, Kl, Vth, Vtl, attn, Ch, Cl);

    // launch 4: output projection: out = ctx @ Wo^T + bo
    gemm_big<0,0,0><<<dim3(DM / 128, (BB * SS) / 128, 1), blk, shm_big>>>(
        nullptr, nullptr, Ch, Cl,
        Wh + 3 * M1, Wl + 3 * M1, nullptr, nullptr,
        out, nullptr, nullptr, nullptr, nullptr,
        bo, nullptr, DM, DM, DM, DM);
}

// round 15
// speedup vs baseline: 1.4126x; 1.0281x over previous
#include <cuda_runtime.h>
#include <cuda_bf16.h>
#include <cstdint>

#define BB 2
#define SS 2048
#define DM 1024
#define NH 16
#define DK 64

typedef unsigned short u16;
typedef unsigned int   u32;

// ---- bf16 hi/lo plane scratch (device globals; no allocation APIs) ----
static __device__ u16 g_Qh [BB*SS*DM], g_Ql [BB*SS*DM];
static __device__ u16 g_Kh [BB*SS*DM], g_Kl [BB*SS*DM];
static __device__ u16 g_Vth[BB*SS*DM], g_Vtl[BB*SS*DM];   // [b][h][dk][s]
static __device__ u16 g_Ch [BB*SS*DM], g_Cl [BB*SS*DM];
static __device__ u16 g_Wh [4*DM*DM],  g_Wl [4*DM*DM];

// ---------------- helpers ----------------
__device__ __forceinline__ u32 smem_u32(const void* p) {
    u32 a;
    asm("{ .reg .u64 t; cvta.to.shared.u64 t, %1; cvt.u32.u64 %0, t; }"
        : "=r"(a) : "l"(p));
    return a;
}
#define SWZ(o) ((o) ^ (((o) >> 3) & 0x70))

__device__ __forceinline__ void split1(float v, u16& h, u16& l) {
    __nv_bfloat16 hb = __float2bfloat16(v);
    h = __bfloat16_as_ushort(hb);
    l = __bfloat16_as_ushort(__float2bfloat16(v - __bfloat162float(hb)));
}

__device__ __forceinline__ void cpa16(u32 s, const void* g) {
    asm volatile("cp.async.cg.shared.global [%0], [%1], 16;" :: "r"(s), "l"(g));
}
__device__ __forceinline__ void cpa_commit() {
    asm volatile("cp.async.commit_group;" ::: "memory");
}
__device__ __forceinline__ void cpa_wait1() {
    asm volatile("cp.async.wait_group 1;" ::: "memory");
}
__device__ __forceinline__ void cpa_wait0() {
    asm volatile("cp.async.wait_group 0;" ::: "memory");
}
__device__ __forceinline__ void ldsm4(u32 a, u32& r0, u32& r1, u32& r2, u32& r3) {
    asm volatile("ldmatrix.sync.aligned.m8n8.x4.shared.b16 {%0,%1,%2,%3}, [%4];"
        : "=r"(r0), "=r"(r1), "=r"(r2), "=r"(r3) : "r"(a));
}

#define MMA_BF16(acc, af, bf)                                                   \
    asm volatile(                                                               \
        "mma.sync.aligned.m16n8k16.row.col.f32.bf16.bf16.f32 "                  \
        "{%0,%1,%2,%3}, {%4,%5,%6,%7}, {%8,%9}, {%0,%1,%2,%3};"                 \
        : "+f"(acc[0]), "+f"(acc[1]), "+f"(acc[2]), "+f"(acc[3])                \
        : "r"(af[0]), "r"(af[1]), "r"(af[2]), "r"(af[3]), "r"(bf[0]), "r"(bf[1]))

// ---------------- big-tile GEMM: C[128x128] = A * B^T (NT), bf16x2 3-term ---------
// (verbatim from round 14; proven)
template <int AFP32, int OUTM, int SEL2>
__global__ __launch_bounds__(256, 2) void gemm_big(
    const float* __restrict__ Af,  const float* __restrict__ Af2,
    const u16* __restrict__ Aph, const u16* __restrict__ Apl,
    const u16* __restrict__ Bph, const u16* __restrict__ Bpl,
    const u16* __restrict__ B2ph, const u16* __restrict__ B2pl,
    float* __restrict__ Cf, u16* __restrict__ Cph, u16* __restrict__ Cpl,
    u16* __restrict__ C2ph, u16* __restrict__ C2pl,
    const float* __restrict__ bias, const float* __restrict__ bias2,
    int lda, int ldb, int ldc, int K)
{
    extern __shared__ char dsm[];
    const u32 sbase = smem_u32(dsm);
    const int tid = threadIdx.x, lane = tid & 31, w = tid >> 5;
    const int wm = (w & 3) << 5;      // warp m offset: 0,32,64,96
    const int wn = (w >> 2) << 6;     // warp n offset: 0,64
    const int g = lane >> 2, t = lane & 3;

    const float* A_f = Af;
    const u16 *AhG = Aph, *AlG = Apl;
    const u16 *BhG = Bph, *BlG = Bpl;
    u16 *COh = Cph, *COl = Cpl;
    const float* bi = bias;
    if (SEL2 && blockIdx.z == 1) {
        A_f = Af2; BhG = B2ph; BlG = B2pl; COh = C2ph; COl = C2pl; bi = bias2;
    }
    const long arow0 = (long)blockIdx.y * 128;
    if (AFP32) { if (A_f) A_f += arow0 * lda; }
    else       { AhG += arow0 * lda; AlG += arow0 * lda; }
    BhG += (long)blockIdx.x * 128 * ldb;
    BlG += (long)blockIdx.x * 128 * ldb;

    float acc[2][8][4];
    #pragma unroll
    for (int i = 0; i < 2; i++)
        #pragma unroll
        for (int j = 0; j < 8; j++)
            #pragma unroll
            for (int c = 0; c < 4; c++) acc[i][j][c] = 0.f;

    u32 a_base[2], b_base[4];
    #pragma unroll
    for (int mi = 0; mi < 2; mi++)
        a_base[mi] = (u32)((wm + mi * 16 + (lane & 15)) * 128 + (lane >> 4) * 16);
    #pragma unroll
    for (int np = 0; np < 4; np++)
        b_base[np] = (u32)((wn + np * 16 + (lane & 7) + ((lane >> 4) << 3)) * 128
                           + ((lane >> 3) & 1) * 16);

    auto issueP = [&](const u16* gh, const u16* gl, int ld, int c, u32 dst) {
        #pragma unroll
        for (int it = 0; it < 4; it++) {
            int i = it * 256 + tid;
            int row = i >> 3, seg = i & 7;
            if (seg < 4) {
                cpa16(dst + SWZ((u32)(row * 128 + seg * 16)),
                      gh + (long)row * ld + c * 32 + seg * 8);
            } else {
                cpa16(dst + SWZ((u32)(row * 128 + 64 + (seg - 4) * 16)),
                      gl + (long)row * ld + c * 32 + (seg - 4) * 8);
            }
        }
    };

    float4 ra[4];
    auto ldgA = [&](int c) {
        #pragma unroll
        for (int it = 0; it < 4; it++) {
            int i = it * 256 + tid;
            int row = i >> 3, cq = (i & 7) << 2;
            ra[it] = *(const float4*)(A_f + (long)row * lda + c * 32 + cq);
        }
    };
    auto stsA = [&](int buf) {
        char* ap = dsm + buf * 16384;
        #pragma unroll
        for (int it = 0; it < 4; it++) {
            int i = it * 256 + tid;
            int row = i >> 3, cq = (i & 7) << 2;
            u16 h0, l0, h1, l1, h2, l2, h3, l3;
            split1(ra[it].x, h0, l0); split1(ra[it].y, h1, l1);
            split1(ra[it].z, h2, l2); split1(ra[it].w, h3, l3);
            *(uint2*)(ap + SWZ((u32)(row * 128 + cq * 2)))
                = make_uint2(h0 | ((u32)h1 << 16), h2 | ((u32)h3 << 16));
            *(uint2*)(ap + SWZ((u32)(row * 128 + 64 + cq * 2)))
                = make_uint2(l0 | ((u32)l1 << 16), l2 | ((u32)l3 << 16));
        }
    };

    auto compute = [&](int buf) {
        u32 ab = sbase + buf * 16384;
        u32 bb = sbase + 32768 + buf * 16384;
        #pragma unroll
        for (int s = 0; s < 2; s++) {
            u32 aH[2][4], aL[2][4];
            #pragma unroll
            for (int mi = 0; mi < 2; mi++) {
                ldsm4(ab + SWZ(a_base[mi] + s * 32),
                      aH[mi][0], aH[mi][1], aH[mi][2], aH[mi][3]);
                ldsm4(ab + SWZ(a_base[mi] + s * 32 + 64),
                      aL[mi][0], aL[mi][1], aL[mi][2], aL[mi][3]);
            }
            #pragma unroll
            for (int np = 0; np < 4; np++) {
                u32 h0, h1, h2, h3, l0, l1, l2, l3;
                ldsm4(bb + SWZ(b_base[np] + s * 32), h0, h1, h2, h3);
                ldsm4(bb + SWZ(b_base[np] + s * 32 + 64), l0, l1, l2, l3);
                u32 bfh[2][2] = {{h0, h1}, {h2, h3}};
                u32 bfl[2][2] = {{l0, l1}, {l2, l3}};
                #pragma unroll
                for (int mi = 0; mi < 2; mi++)
                    #pragma unroll
                    for (int sub = 0; sub < 2; sub++) {
                        int ni = np * 2 + sub;
                        MMA_BF16(acc[mi][ni], aH[mi], bfh[sub]);
                        MMA_BF16(acc[mi][ni], aH[mi], bfl[sub]);
                        MMA_BF16(acc[mi][ni], aL[mi], bfh[sub]);
                    }
            }
        }
    };

    const int nch = K >> 5;
    if (AFP32) ldgA(0); else issueP(AhG, AlG, lda, 0, sbase);
    issueP(BhG, BlG, ldb, 0, sbase + 32768);
    cpa_commit();

    for (int c = 0; c < nch; c++) {
        const int buf = c & 1;
        if (AFP32) stsA(buf);
        if (c + 1 < nch) {
            const int nb = buf ^ 1;
            if (!AFP32) issueP(AhG, AlG, lda, c + 1, sbase + nb * 16384);
            issueP(BhG, BlG, ldb, c + 1, sbase + 32768 + nb * 16384);
            cpa_commit();
            if (AFP32) ldgA(c + 1);
            cpa_wait1();
        } else {
            cpa_wait0();
        }
        __syncthreads();
        compute(buf);
        __syncthreads();
    }

    if (OUTM == 0) {
        float* C = Cf + arow0 * ldc + blockIdx.x * 128;
        #pragma unroll
        for (int mi = 0; mi < 2; mi++) {
            int r0 = wm + mi * 16 + g;
            #pragma unroll
            for (int ni = 0; ni < 8; ni++) {
                int c0 = wn + ni * 8 + (t << 1);
                float bv0 = bi[blockIdx.x * 128 + c0];
                float bv1 = bi[blockIdx.x * 128 + c0 + 1];
                *(float2*)(C + (long)r0 * ldc + c0)
                    = make_float2(acc[mi][ni][0] + bv0, acc[mi][ni][1] + bv1);
                *(float2*)(C + (long)(r0 + 8) * ldc + c0)
                    = make_float2(acc[mi][ni][2] + bv0, acc[mi][ni][3] + bv1);
            }
        }
    } else if (OUTM == 1) {
        u16* Ph = COh + arow0 * ldc + blockIdx.x * 128;
        u16* Pl = COl + arow0 * ldc + blockIdx.x * 128;
        #pragma unroll
        for (int mi = 0; mi < 2; mi++) {
            int r0 = wm + mi * 16 + g;
            #pragma unroll
            for (int ni = 0; ni < 8; ni++) {
                int c0 = wn + ni * 8 + (t << 1);
                float bv0 = bi[blockIdx.x * 128 + c0];
                float bv1 = bi[blockIdx.x * 128 + c0 + 1];
                float v00 = acc[mi][ni][0] + bv0, v01 = acc[mi][ni][1] + bv1;
                float v10 = acc[mi][ni][2] + bv0, v11 = acc[mi][ni][3] + bv1;
                u16 h00, l00, h01, l01, h10, l10, h11, l11;
                split1(v00, h00, l00); split1(v01, h01, l01);
                split1(v10, h10, l10); split1(v11, h11, l11);
                *(u32*)(Ph + (long)r0 * ldc + c0)       = h00 | ((u32)h01 << 16);
                *(u32*)(Pl + (long)r0 * ldc + c0)       = l00 | ((u32)l01 << 16);
                *(u32*)(Ph + (long)(r0 + 8) * ldc + c0) = h10 | ((u32)h11 << 16);
                *(u32*)(Pl + (long)(r0 + 8) * ldc + c0) = l10 | ((u32)l11 << 16);
            }
        }
    } else {
        float* epi = (float*)dsm;
        #pragma unroll
        for (int mi = 0; mi < 2; mi++) {
            int r0 = wm + mi * 16 + g;
            #pragma unroll
            for (int ni = 0; ni < 8; ni++) {
                int c0 = wn + ni * 8 + (t << 1);
                epi[r0 * 129 + c0]           = acc[mi][ni][0];
                epi[r0 * 129 + c0 + 1]       = acc[mi][ni][1];
                epi[(r0 + 8) * 129 + c0]     = acc[mi][ni][2];
                epi[(r0 + 8) * 129 + c0 + 1] = acc[mi][ni][3];
            }
        }
        __syncthreads();
        #pragma unroll
        for (int it = 0; it < 64; it++) {
            int i = it * 256 + tid;
            int n = i >> 7, m = i & 127;
            float v = epi[m * 129 + n] + bi[blockIdx.x * 128 + n];
            int h = (blockIdx.x << 1) + (n >> 6), dk = n & 63;
            long grow = arow0 + m;
            long b = grow >> 11, s = grow & 2047;
            long addr = ((b * NH + h) * (long)DK + dk) * SS + s;
            u16 hh, ll;
            split1(v, hh, ll);
            COh[addr] = hh;
            COl[addr] = ll;
        }
    }
}

// ---------------- fused scores+softmax+PV (flash-style, attn written once) ----------
// Round-15 change: __launch_bounds__(256, 2) for 2 CTAs/SM (was reg-limited to 1),
// plus per-np fragment load+consume in both MMA loops to cut live register pressure.
// Arithmetic (MMA order/count, 3-term scheme) unchanged.
__global__ __launch_bounds__(256, 2) void fused_attn(
    const u16* __restrict__ Qh, const u16* __restrict__ Ql,
    const u16* __restrict__ Kh, const u16* __restrict__ Kl,
    const u16* __restrict__ Vh, const u16* __restrict__ Vl,
    float* __restrict__ attn, u16* __restrict__ Cph, u16* __restrict__ Cpl)
{
    extern __shared__ char dsm[];
    const u32 sb = smem_u32(dsm);
    const int tid = threadIdx.x, lane = tid & 31, w = tid >> 5;
    const int wm = w << 4;                  // 16 rows per warp
    const int g = lane >> 2, t = lane & 3;
    const int z = blockIdx.z, b = z / NH, h = z % NH;
    const int q0 = blockIdx.y * 128;

    {
        const u16* gqh = Qh + ((long)b * SS + q0) * DM + h * DK;
        const u16* gql = Ql + ((long)b * SS + q0) * DM + h * DK;
        #pragma unroll
        for (int it = 0; it < 4; it++) {
            int i = it * 256 + tid;
            int row = i >> 3, cc = i & 7;
            u32 so = SWZ((u32)(row * 128 + cc * 16));
            cpa16(sb + so,         gqh + (long)row * DM + cc * 8);
            cpa16(sb + 16384 + so, gql + (long)row * DM + cc * 8);
        }
    }

    const u32 a_base = (u32)((wm + (lane & 15)) * 128 + (lane >> 4) * 16);
    u32 b_base[4];
    #pragma unroll
    for (int np = 0; np < 4; np++) {
        int n = np * 16 + (lane & 7) + ((lane >> 4) << 3);
        b_base[np] = (u32)(n * 128 + ((lane >> 3) & 1) * 16);
    }

    auto issueK = [&](int c, int buf) {
        u32 kh = sb + 32768 + buf * 16384, kl = kh + 8192;
        const u16* gh = Kh + ((long)b * SS + c * 64) * DM + h * DK;
        const u16* gl = Kl + ((long)b * SS + c * 64) * DM + h * DK;
        #pragma unroll
        for (int it = 0; it < 2; it++) {
            int i = it * 256 + tid;
            int row = i >> 3, cc = i & 7;
            u32 so = SWZ((u32)(row * 128 + cc * 16));
            cpa16(kh + so, gh + (long)row * DM + cc * 8);
            cpa16(kl + so, gl + (long)row * DM + cc * 8);
        }
    };
    auto issueV = [&](int c, int buf) {
        u32 vh = sb + 65536 + buf * 16384, vl = vh + 8192;
        const u16* gh = Vh + ((long)(b * NH + h) * DK) * SS + c * 64;
        const u16* gl = Vl + ((long)(b * NH + h) * DK) * SS + c * 64;
        #pragma unroll
        for (int it = 0; it < 2; it++) {
            int i = it * 256 + tid;
            int row = i >> 3, cc = i & 7;
            u32 so = SWZ((u32)(row * 128 + cc * 16));
            cpa16(vh + so, gh + (long)row * SS + cc * 8);
            cpa16(vl + so, gl + (long)row * SS + cc * 8);
        }
    };

    float sacc[8][4];
    auto computeS = [&](int buf) {
        #pragma unroll
        for (int ni = 0; ni < 8; ni++)
            #pragma unroll
            for (int c4 = 0; c4 < 4; c4++) sacc[ni][c4] = 0.f;
        u32 kh = sb + 32768 + buf * 16384, kl = kh + 8192;
        #pragma unroll
        for (int s = 0; s < 4; s++) {
            u32 aH[4], aL[4];
            u32 o = SWZ(a_base + s * 32);
            ldsm4(sb + o,         aH[0], aH[1], aH[2], aH[3]);
            ldsm4(sb + 16384 + o, aL[0], aL[1], aL[2], aL[3]);
            #pragma unroll
            for (int np = 0; np < 4; np++) {
                u32 ob = SWZ(b_base[np] + s * 32);
                u32 h0, h1, h2, h3, l0, l1, l2, l3;
                ldsm4(kh + ob, h0, h1, h2, h3);
                ldsm4(kl + ob, l0, l1, l2, l3);
                u32 bfh[2][2] = {{h0, h1}, {h2, h3}};
                u32 bfl[2][2] = {{l0, l1}, {l2, l3}};
                #pragma unroll
                for (int sub = 0; sub < 2; sub++) {
                    int ni = np * 2 + sub;
                    MMA_BF16(sacc[ni], aH, bfh[sub]);
                    MMA_BF16(sacc[ni], aH, bfl[sub]);
                    MMA_BF16(sacc[ni], aL, bfh[sub]);
                }
            }
        }
    };

    // Phase A: online row max + sum
    float mr0 = -1e30f, mr1 = -1e30f, sr0 = 0.f, sr1 = 0.f;
    issueK(0, 0);
    cpa_commit();
    for (int c = 0; c < SS / 64; c++) {
        const int buf = c & 1;
        if (c + 1 < SS / 64) { issueK(c + 1, buf ^ 1); cpa_commit(); cpa_wait1(); }
        else cpa_wait0();
        __syncthreads();
        computeS(buf);
        #pragma unroll
        for (int ni = 0; ni < 8; ni++)
            #pragma unroll
            for (int c4 = 0; c4 < 4; c4++) sacc[ni][c4] *= 0.125f;
        float lm0 = -1e30f, lm1 = -1e30f;
        #pragma unroll
        for (int ni = 0; ni < 8; ni++) {
            lm0 = fmaxf(lm0, fmaxf(sacc[ni][0], sacc[ni][1]));
            lm1 = fmaxf(lm1, fmaxf(sacc[ni][2], sacc[ni][3]));
        }
        lm0 = fmaxf(lm0, __shfl_xor_sync(0xffffffffu, lm0, 1));
        lm0 = fmaxf(lm0, __shfl_xor_sync(0xffffffffu, lm0, 2));
        lm1 = fmaxf(lm1, __shfl_xor_sync(0xffffffffu, lm1, 1));
        lm1 = fmaxf(lm1, __shfl_xor_sync(0xffffffffu, lm1, 2));
        float mn0 = fmaxf(mr0, lm0), mn1 = fmaxf(mr1, lm1);
        sr0 *= __expf(mr0 - mn0); sr1 *= __expf(mr1 - mn1);
        mr0 = mn0; mr1 = mn1;
        float s0 = 0.f, s1 = 0.f;
        #pragma unroll
        for (int ni = 0; ni < 8; ni++) {
            s0 += __expf(sacc[ni][0] - mr0) + __expf(sacc[ni][1] - mr0);
            s1 += __expf(sacc[ni][2] - mr1) + __expf(sacc[ni][3] - mr1);
        }
        s0 += __shfl_xor_sync(0xffffffffu, s0, 1);
        s0 += __shfl_xor_sync(0xffffffffu, s0, 2);
        s1 += __shfl_xor_sync(0xffffffffu, s1, 1);
        s1 += __shfl_xor_sync(0xffffffffu, s1, 2);
        sr0 += s0; sr1 += s1;
        __syncthreads();
    }
    const float is0 = 1.f / sr0, is1 = 1.f / sr1;

    // Phase B: P write + O accumulation
    float oacc[8][4];
    #pragma unroll
    for (int nd = 0; nd < 8; nd++)
        #pragma unroll
        for (int c4 = 0; c4 < 4; c4++) oacc[nd][c4] = 0.f;

    float* attnB = attn + ((long)(b * NH + h) * SS + q0) * SS;
    issueK(0, 0); issueV(0, 0);
    cpa_commit();
    for (int c = 0; c < SS / 64; c++) {
        const int buf = c & 1;
        if (c + 1 < SS / 64) {
            issueK(c + 1, buf ^ 1); issueV(c + 1, buf ^ 1);
            cpa_commit(); cpa_wait1();
        } else cpa_wait0();
        __syncthreads();
        computeS(buf);
        const int r0 = wm + g, r1 = wm + 8 + g;
        #pragma unroll
        for (int ni = 0; ni < 8; ni++) {
            float p0 = __expf(fmaf(sacc[ni][0], 0.125f, -mr0)) * is0;
            float p1 = __expf(fmaf(sacc[ni][1], 0.125f, -mr0)) * is0;
            float p2 = __expf(fmaf(sacc[ni][2], 0.125f, -mr1)) * is1;
            float p3 = __expf(fmaf(sacc[ni][3], 0.125f, -mr1)) * is1;
            int col = c * 64 + ni * 8 + (t << 1);
            *(float2*)(attnB + (long)r0 * SS + col) = make_float2(p0, p1);
            *(float2*)(attnB + (long)r1 * SS + col) = make_float2(p2, p3);
            sacc[ni][0] = p0; sacc[ni][1] = p1; sacc[ni][2] = p2; sacc[ni][3] = p3;
        }
        u32 vh = sb + 65536 + buf * 16384, vl = vh + 8192;
        #pragma unroll
        for (int s = 0; s < 4; s++) {
            u32 aH[4], aL[4];
            #pragma unroll
            for (int q = 0; q < 2; q++) {
                u16 ha, la, hb, lb;
                split1(sacc[2 * s + q][0], ha, la);
                split1(sacc[2 * s + q][1], hb, lb);
                aH[q * 2]     = ha | ((u32)hb << 16);
                aL[q * 2]     = la | ((u32)lb << 16);
                split1(sacc[2 * s + q][2], ha, la);
                split1(sacc[2 * s + q][3], hb, lb);
                aH[q * 2 + 1] = ha | ((u32)hb << 16);
                aL[q * 2 + 1] = la | ((u32)lb << 16);
            }
            #pragma unroll
            for (int np = 0; np < 4; np++) {
                u32 ob = SWZ(b_base[np] + s * 32);
                u32 h0, h1, h2, h3, l0, l1, l2, l3;
                ldsm4(vh + ob, h0, h1, h2, h3);
                ldsm4(vl + ob, l0, l1, l2, l3);
                u32 bvh[2][2] = {{h0, h1}, {h2, h3}};
                u32 bvl[2][2] = {{l0, l1}, {l2, l3}};
                #pragma unroll
                for (int sub = 0; sub < 2; sub++) {
                    int nd = np * 2 + sub;
                    MMA_BF16(oacc[nd], aH, bvh[sub]);
                    MMA_BF16(oacc[nd], aH, bvl[sub]);
                    MMA_BF16(oacc[nd], aL, bvh[sub]);
                }
            }
        }
        __syncthreads();
    }

    u16* PhC = Cph + ((long)b * SS + q0) * DM + h * DK;
    u16* PlC = Cpl + ((long)b * SS + q0) * DM + h * DK;
    const int r0 = wm + g, r1 = wm + 8 + g;
    #pragma unroll
    for (int nd = 0; nd < 8; nd++) {
        int col = nd * 8 + (t << 1);
        u16 h0, l0, h1, l1;
        split1(oacc[nd][0], h0, l0); split1(oacc[nd][1], h1, l1);
        *(u32*)(PhC + (long)r0 * DM + col) = h0 | ((u32)h1 << 16);
        *(u32*)(PlC + (long)r0 * DM + col) = l0 | ((u32)l1 << 16);
        split1(oacc[nd][2], h0, l0); split1(oacc[nd][3], h1, l1);
        *(u32*)(PhC + (long)r1 * DM + col) = h0 | ((u32)h1 << 16);
        *(u32*)(PlC + (long)r1 * DM + col) = l0 | ((u32)l1 << 16);
    }
}

// ---------------- weight converter: 4 weights -> bf16 hi/lo planes, ONE launch ------
__global__ __launch_bounds__(256) void splitw4(
    const float* __restrict__ w0, const float* __restrict__ w1,
    const float* __restrict__ w2, const float* __restrict__ w3,
    u16* __restrict__ ph, u16* __restrict__ pl)
{
    long i = ((long)blockIdx.x * 256 + threadIdx.x) * 4;  // [0, 4*DM*DM)
    int sel = (int)(i >> 20);
    const float* src = (sel == 0) ? w0 : (sel == 1) ? w1 : (sel == 2) ? w2 : w3;
    long j = i & (DM * DM - 1);
    float4 v = *(const float4*)(src + j);
    u16 h0, l0, h1, l1, h2, l2, h3, l3;
    split1(v.x, h0, l0); split1(v.y, h1, l1);
    split1(v.z, h2, l2); split1(v.w, h3, l3);
    *(uint2*)(ph + i) = make_uint2(h0 | ((u32)h1 << 16), h2 | ((u32)h3 << 16));
    *(uint2*)(pl + i) = make_uint2(l0 | ((u32)l1 << 16), l2 | ((u32)l3 << 16));
}

extern "C" void kernel_launch(void* const* d_in, const int* in_sizes, int n_in,
                              void* d_out, int out_size)
{
    (void)in_sizes; (void)n_in; (void)out_size;

    const float* q  = (const float*)d_in[0];
    const float* k  = (const float*)d_in[1];
    const float* vv = (const float*)d_in[2];
    const float* Wq = (const float*)d_in[3];
    const float* bq = (const float*)d_in[4];
    const float* Wk = (const float*)d_in[5];
    const float* bk = (const float*)d_in[6];
    const float* Wv = (const float*)d_in[7];
    const float* bv = (const float*)d_in[8];
    const float* Wo = (const float*)d_in[9];
    const float* bo = (const float*)d_in[10];

    float* out  = (float*)d_out;                 // [B,S,D]
    float* attn = out + (long)BB * SS * DM;      // [B,H,S,S]

    u16 *Qh, *Ql, *Kh, *Kl, *Vth, *Vtl, *Ch, *Cl, *Wh, *Wl;
    cudaGetSymbolAddress((void**)&Qh,  g_Qh);  cudaGetSymbolAddress((void**)&Ql,  g_Ql);
    cudaGetSymbolAddress((void**)&Kh,  g_Kh);  cudaGetSymbolAddress((void**)&Kl,  g_Kl);
    cudaGetSymbolAddress((void**)&Vth, g_Vth); cudaGetSymbolAddress((void**)&Vtl, g_Vtl);
    cudaGetSymbolAddress((void**)&Ch,  g_Ch);  cudaGetSymbolAddress((void**)&Cl,  g_Cl);
    cudaGetSymbolAddress((void**)&Wh,  g_Wh);  cudaGetSymbolAddress((void**)&Wl,  g_Wl);

    const int shm_big = 66048;
    const int shm_f   = 98304;
    cudaFuncSetAttribute(gemm_big<1,1,1>, cudaFuncAttributeMaxDynamicSharedMemorySize, shm_big);
    cudaFuncSetAttribute(gemm_big<1,2,0>, cudaFuncAttributeMaxDynamicSharedMemorySize, shm_big);
    cudaFuncSetAttribute(gemm_big<0,0,0>, cudaFuncAttributeMaxDynamicSharedMemorySize, shm_big);
    cudaFuncSetAttribute(fused_attn,      cudaFuncAttributeMaxDynamicSharedMemorySize, shm_f);

    dim3 blk(256);
    const int M1 = DM * DM;

    // launch 0: all weight planes
    splitw4<<<4 * M1 / 1024, blk>>>(Wq, Wk, Wv, Wo, Wh, Wl);

    // launch 1: Q and K projections merged (z selects operand set)
    gemm_big<1,1,1><<<dim3(DM / 128, (BB * SS) / 128, 2), blk, shm_big>>>(
        q, k, nullptr, nullptr,
        Wh + 0 * M1, Wl + 0 * M1, Wh + 1 * M1, Wl + 1 * M1,
        nullptr, Qh, Ql, Kh, Kl,
        bq, bk, DM, DM, DM, DM);

    // launch 2: V projection -> V^T planes per head
    gemm_big<1,2,0><<<dim3(DM / 128, (BB * SS) / 128, 1), blk, shm_big>>>(
        vv, nullptr, nullptr, nullptr,
        Wh + 2 * M1, Wl + 2 * M1, nullptr, nullptr,
        nullptr, Vth, Vtl, nullptr, nullptr,
        bv, nullptr, DM, DM, 0, DM);

    // launch 3 (ncu-captured): fused scores + softmax + PV (attn written once)
    fused_attn<<<dim3(1, SS / 128, BB * NH), blk, shm_f>>>(
        Qh, Ql, Kh, Kl, Vth, Vtl, attn, Ch, Cl);

    // launch 4: output projection: out = ctx @ Wo^T + bo
    gemm_big<0,0,0><<<dim3(DM / 128, (BB * SS) / 128, 1), blk, shm_big>>>(
        nullptr, nullptr, Ch, Cl,
        Wh + 3 * M1, Wl + 3 * M1, nullptr, nullptr,
        out, nullptr, nullptr, nullptr, nullptr,
        bo, nullptr, DM, DM, DM, DM);
}